// round 3
// baseline (speedup 1.0000x reference)
#include <cuda_runtime.h>
#include <cuda_fp16.h>
#include <cstdint>

#define SEQ   64
#define BATCH 64
#define EMBD  512
#define HID   1024
#define VOCAB 32000
#define SB    (SEQ*BATCH)
#define H3    (3*HID)

// ---------------- device scratch (no cudaMalloc allowed) ----------------
__device__ __half g_E[SB*EMBD];
__device__ __half g_wih[H3*EMBD];
__device__ __half g_wout[(size_t)VOCAB*HID];
__device__ float  g_gi[(size_t)SB*H3];
__device__ __half g_hs[(size_t)SB*HID];
__device__ __half g_h16[2][BATCH*HID];
__device__ unsigned g_bar_count = 0;
__device__ volatile unsigned g_bar_sense = 0;

// ---------------- ptx helpers ----------------
__device__ __forceinline__ uint32_t smem_u32(const void* p){
    return (uint32_t)__cvta_generic_to_shared(p);
}
__device__ __forceinline__ void ldsm_x4(uint32_t&a0,uint32_t&a1,uint32_t&a2,uint32_t&a3,uint32_t addr){
    asm volatile("ldmatrix.sync.aligned.m8n8.x4.shared.b16 {%0,%1,%2,%3},[%4];"
                 :"=r"(a0),"=r"(a1),"=r"(a2),"=r"(a3):"r"(addr));
}
__device__ __forceinline__ void ldsm_x2(uint32_t&b0,uint32_t&b1,uint32_t addr){
    asm volatile("ldmatrix.sync.aligned.m8n8.x2.shared.b16 {%0,%1},[%2];"
                 :"=r"(b0),"=r"(b1):"r"(addr));
}
__device__ __forceinline__ void mma16816(float&d0,float&d1,float&d2,float&d3,
                                         uint32_t a0,uint32_t a1,uint32_t a2,uint32_t a3,
                                         uint32_t b0,uint32_t b1){
    asm volatile("mma.sync.aligned.m16n8k16.row.col.f32.f16.f16.f32 "
                 "{%0,%1,%2,%3},{%4,%5,%6,%7},{%8,%9},{%0,%1,%2,%3};"
                 :"+f"(d0),"+f"(d1),"+f"(d2),"+f"(d3)
                 :"r"(a0),"r"(a1),"r"(a2),"r"(a3),"r"(b0),"r"(b1));
}
__device__ __forceinline__ void cp16(uint32_t saddr, const void* g){
    asm volatile("cp.async.cg.shared.global [%0],[%1],16;"::"r"(saddr),"l"(g));
}
__device__ __forceinline__ void cp_commit(){ asm volatile("cp.async.commit_group;"); }
template<int N> __device__ __forceinline__ void cp_wait(){ asm volatile("cp.async.wait_group %0;"::"n"(N)); }

// ---------------- prep kernels ----------------
__global__ void k_cvt(const float* __restrict__ src, __half* __restrict__ dst, int n2){
    int i = blockIdx.x*blockDim.x + threadIdx.x;
    if (i < n2){
        float2 v = reinterpret_cast<const float2*>(src)[i];
        reinterpret_cast<__half2*>(dst)[i] = __floats2half2_rn(v.x, v.y);
    }
}
__global__ void k_embed(const int* __restrict__ x, const float* __restrict__ emb){
    int i = blockIdx.x*blockDim.x + threadIdx.x;
    if (i >= SB*EMBD/2) return;
    int row = i/(EMBD/2), cp = i%(EMBD/2);
    int s = row>>6, b = row&63;
    int tok = (s==0) ? 2 : x[(s-1)*BATCH + b];
    float2 v = reinterpret_cast<const float2*>(emb + (size_t)tok*EMBD)[cp];
    float a0 = (tok==0)?0.f:fmaxf(v.x,0.f);
    float a1 = (tok==0)?0.f:fmaxf(v.y,0.f);
    reinterpret_cast<__half2*>(g_E)[i] = __floats2half2_rn(a0, a1);
}
__global__ void k_inith(const float* __restrict__ hidden){
    int i = blockIdx.x*blockDim.x + threadIdx.x;
    if (i < BATCH*HID) g_h16[0][i] = __float2half(hidden[i]);
}

// ---------------- fp16 GEMM: C(MxN) = A(MxK) @ Bw(NxK)^T + bias ----------------
#define BMT 128
#define BNT 128
#define BKT 32
#define PADK 40

template<bool PERMUTE>
__global__ __launch_bounds__(256)
void gemm_f16(const __half* __restrict__ A, const __half* __restrict__ Bw,
              const float* __restrict__ bias, float* __restrict__ C, int K, int N){
    __shared__ __half sA[2][BMT][PADK];
    __shared__ __half sB[2][BNT][PADK];
    int tid = threadIdx.x;
    int bm = blockIdx.y, bn = blockIdx.x;
    const __half* Ab = A + (size_t)bm*BMT*K;
    const __half* Bb = Bw + (size_t)bn*BNT*K;

    auto load_stage = [&](int stg, int kt){
        int k0 = kt*BKT;
        #pragma unroll
        for (int i=0;i<2;i++){
            int c = tid + i*256;
            int row = c>>2, col8 = (c&3)*8;
            cp16(smem_u32(&sA[stg][row][col8]), Ab + (size_t)row*K + k0 + col8);
            cp16(smem_u32(&sB[stg][row][col8]), Bb + (size_t)row*K + k0 + col8);
        }
    };
    int NK = K/BKT;
    load_stage(0,0); cp_commit();
    load_stage(1,1); cp_commit();

    int warp = tid>>5, lane = tid&31;
    int wm = warp&1, wn = warp>>1;      // warp tile 64(m) x 32(n)
    float acc[4][4][4];
    #pragma unroll
    for(int mi=0;mi<4;mi++) for(int ni=0;ni<4;ni++) for(int d=0;d<4;d++) acc[mi][ni][d]=0.f;

    for (int kt=0; kt<NK; kt++){
        if (kt==NK-1) cp_wait<0>(); else cp_wait<1>();
        __syncthreads();
        int stg = kt&1;
        #pragma unroll
        for (int kk=0; kk<2; kk++){
            uint32_t a[4][4], b[4][2];
            #pragma unroll
            for(int mi=0;mi<4;mi++){
                int row = wm*64 + mi*16 + (lane&15);
                int col = kk*16 + (lane>>4)*8;
                ldsm_x4(a[mi][0],a[mi][1],a[mi][2],a[mi][3], smem_u32(&sA[stg][row][col]));
            }
            #pragma unroll
            for(int ni=0;ni<4;ni++){
                int row = wn*32 + ni*8 + (lane&7);
                int col = kk*16 + ((lane>>3)&1)*8;
                ldsm_x2(b[ni][0],b[ni][1], smem_u32(&sB[stg][row][col]));
            }
            #pragma unroll
            for(int mi=0;mi<4;mi++)
                #pragma unroll
                for(int ni=0;ni<4;ni++)
                    mma16816(acc[mi][ni][0],acc[mi][ni][1],acc[mi][ni][2],acc[mi][ni][3],
                             a[mi][0],a[mi][1],a[mi][2],a[mi][3], b[ni][0],b[ni][1]);
        }
        __syncthreads();
        if (kt+2 < NK){ load_stage(kt&1, kt+2); cp_commit(); }
    }

    int mbase = bm*BMT + wm*64;
    int nbase = bn*BNT + wn*32;
    #pragma unroll
    for(int mi=0;mi<4;mi++){
        int r0 = mbase + mi*16 + (lane>>2);
        #pragma unroll
        for(int ni=0;ni<4;ni++){
            int cc = nbase + ni*8 + 2*(lane&3);
            float bv0 = bias[cc], bv1 = bias[cc+1];
            int rr = r0;
            size_t ro = PERMUTE ? (size_t)((rr&63)*64 + (rr>>6))*N : (size_t)rr*N;
            *reinterpret_cast<float2*>(C + ro + cc) = make_float2(acc[mi][ni][0]+bv0, acc[mi][ni][1]+bv1);
            rr = r0+8;
            ro = PERMUTE ? (size_t)((rr&63)*64 + (rr>>6))*N : (size_t)rr*N;
            *reinterpret_cast<float2*>(C + ro + cc) = make_float2(acc[mi][ni][2]+bv0, acc[mi][ni][3]+bv1);
        }
    }
}

// ---------------- persistent recurrence ----------------
// 64 CTAs x 256 thr. CTA c owns H-columns [c*16, c*16+16); computes 3 gates (48 outs).
#define RC_CTAS 64
#define SW_STRIDE 1032
#define SH_STRIDE 264
#define RC_SMEM (48*SW_STRIDE*2 + 64*SH_STRIDE*2 + 64*48*4)

__global__ __launch_bounds__(256)
void k_recur(const float* __restrict__ w_hh, const float* __restrict__ b_hh,
             const float* __restrict__ hidden){
    extern __shared__ char smem[];
    __half* sW  = (__half*)smem;
    __half* sH  = (__half*)(smem + 48*SW_STRIDE*2);
    float*  sGH = (float*)(smem + 48*SW_STRIDE*2 + 64*SH_STRIDE*2);
    int tid = threadIdx.x, cta = blockIdx.x;
    int j0 = cta*16;

    for (int idx = tid; idx < 48*HID; idx += 256){
        int r = idx>>10, k = idx&1023;
        int g = r>>4, jr = r&15;
        sW[r*SW_STRIDE + k] = __float2half(w_hh[(size_t)(g*HID + j0 + jr)*HID + k]);
    }
    float bh0[4], bh1[4], bh2[4], hold[4];
    #pragma unroll
    for (int t=0;t<4;t++){
        int o = tid + t*256; int b = o>>4, jj = o&15; int j = j0+jj;
        bh0[t]=b_hh[j]; bh1[t]=b_hh[HID+j]; bh2[t]=b_hh[2*HID+j];
        hold[t]=hidden[b*HID + j];
    }
    int warp=tid>>5, lane=tid&31;
    int wm = warp&3, wn = warp>>2;     // m: wm*16 (batch), n: wn*24 (outputs)
    __syncthreads();

    for (int s=0; s<SEQ; s++){
        const __half* hb = g_h16[s&1];
        float acc[3][4];
        #pragma unroll
        for(int ni=0;ni<3;ni++) for(int d=0;d<4;d++) acc[ni][d]=0.f;

        for (int ch=0; ch<4; ch++){
            __syncthreads();
            #pragma unroll
            for (int i=0;i<8;i++){
                int lin = tid + i*256;
                int row = lin>>5, c16 = lin&31;
                uint4 v = __ldcg(reinterpret_cast<const uint4*>(hb + row*HID + ch*256 + c16*8));
                *reinterpret_cast<uint4*>(&sH[row*SH_STRIDE + c16*8]) = v;
            }
            __syncthreads();
            #pragma unroll
            for (int k16=0;k16<16;k16++){
                uint32_t a0,a1,a2,a3;
                int arow = wm*16 + (lane&15);
                int acol = k16*16 + (lane>>4)*8;
                ldsm_x4(a0,a1,a2,a3, smem_u32(&sH[arow*SH_STRIDE + acol]));
                #pragma unroll
                for (int ni=0;ni<3;ni++){
                    uint32_t b0,b1;
                    int brow = wn*24 + ni*8 + (lane&7);
                    int bcol = ch*256 + k16*16 + ((lane>>3)&1)*8;
                    ldsm_x2(b0,b1, smem_u32(&sW[brow*SW_STRIDE + bcol]));
                    mma16816(acc[ni][0],acc[ni][1],acc[ni][2],acc[ni][3],a0,a1,a2,a3,b0,b1);
                }
            }
        }
        __syncthreads();
        {
            int r = wm*16 + (lane>>2);
            #pragma unroll
            for(int ni=0;ni<3;ni++){
                int cc = wn*24 + ni*8 + 2*(lane&3);
                sGH[r*48 + cc]       = acc[ni][0];
                sGH[r*48 + cc+1]     = acc[ni][1];
                sGH[(r+8)*48 + cc]   = acc[ni][2];
                sGH[(r+8)*48 + cc+1] = acc[ni][3];
            }
        }
        __syncthreads();
        __half* hwr = g_h16[(s+1)&1];
        #pragma unroll
        for (int t=0;t<4;t++){
            int o = tid + t*256; int b = o>>4, jj = o&15; int j = j0+jj;
            const float* gi = g_gi + (size_t)(s*BATCH + b)*H3;
            float ir = gi[j], iz = gi[HID+j], inn = gi[2*HID+j];
            float hr = sGH[b*48+jj]    + bh0[t];
            float hz = sGH[b*48+16+jj] + bh1[t];
            float hn = sGH[b*48+32+jj] + bh2[t];
            float rg = 1.f/(1.f+__expf(-(ir+hr)));
            float zg = 1.f/(1.f+__expf(-(iz+hz)));
            float ng = tanhf(inn + rg*hn);
            float hnew = (1.f - zg)*ng + zg*hold[t];
            hold[t] = hnew;
            unsigned short hb16 = __half_as_ushort(__float2half(hnew));
            __stcg(reinterpret_cast<unsigned short*>(hwr + b*HID + j), hb16);
            __stcg(reinterpret_cast<unsigned short*>(g_hs + (size_t)(s*BATCH + b)*HID + j), hb16);
        }
        if (s < SEQ-1){
            __threadfence();
            __syncthreads();
            if (tid==0){
                unsigned old = g_bar_sense;
                unsigned a = atomicAdd(&g_bar_count, 1u);
                if (a == RC_CTAS-1){
                    g_bar_count = 0;
                    __threadfence();
                    atomicExch((unsigned*)&g_bar_sense, old+1u);
                } else {
                    while (g_bar_sense == old) __nanosleep(32);
                }
                __threadfence();
            }
            __syncthreads();
        }
    }
}

// ---------------- launch ----------------
extern "C" void kernel_launch(void* const* d_in, const int* in_sizes, int n_in,
                              void* d_out, int out_size){
    const int*   x      = (const int*)  d_in[0];
    const float* hidden = (const float*)d_in[1];
    const float* emb    = (const float*)d_in[2];
    const float* w_ih   = (const float*)d_in[3];
    const float* w_hh   = (const float*)d_in[4];
    const float* b_ih   = (const float*)d_in[5];
    const float* b_hh   = (const float*)d_in[6];
    const float* w_out  = (const float*)d_in[7];
    const float* b_out  = (const float*)d_in[8];
    float* out = (float*)d_out;

    __half *pE, *pWih, *pWout, *pHs;
    float  *pGi;
    cudaGetSymbolAddress((void**)&pE,    g_E);
    cudaGetSymbolAddress((void**)&pWih,  g_wih);
    cudaGetSymbolAddress((void**)&pWout, g_wout);
    cudaGetSymbolAddress((void**)&pGi,   g_gi);
    cudaGetSymbolAddress((void**)&pHs,   g_hs);

    cudaFuncSetAttribute(k_recur, cudaFuncAttributeMaxDynamicSharedMemorySize, RC_SMEM);

    {   int n2 = (int)((size_t)VOCAB*HID/2);
        k_cvt<<<(n2+255)/256,256>>>(w_out, pWout, n2); }
    {   int n2 = H3*EMBD/2;
        k_cvt<<<(n2+255)/256,256>>>(w_ih, pWih, n2); }
    k_embed<<<(SB*EMBD/2+255)/256,256>>>(x, emb);
    k_inith<<<(BATCH*HID+255)/256,256>>>(hidden);

    // gi = relu(E) @ w_ih^T + b_ih   (4096 x 3072, K=512)
    gemm_f16<false><<<dim3(H3/BNT, SB/BMT), 256>>>(pE, pWih, b_ih, pGi, EMBD, H3);

    // sequential GRU
    k_recur<<<RC_CTAS, 256, RC_SMEM>>>(w_hh, b_hh, hidden);

    // logits = hs @ w_out^T + b_out, permuted rows (s,b) -> (b,s)
    gemm_f16<true><<<dim3(VOCAB/BNT, SB/BMT), 256>>>(pHs, pWout, b_out, out, HID, VOCAB);
}

// round 7
// speedup vs baseline: 1.0568x; 1.0568x over previous
#include <cuda_runtime.h>
#include <cuda_fp16.h>
#include <cstdint>

#define SEQ   64
#define BATCH 64
#define EMBD  512
#define HID   1024
#define VOCAB 32000
#define SB    (SEQ*BATCH)
#define H3    (3*HID)

// ---------------- device scratch (no cudaMalloc allowed) ----------------
__device__ __half g_E[SB*EMBD];
__device__ __half g_wih[H3*EMBD];
__device__ __half g_wout[(size_t)VOCAB*HID];
__device__ float  g_gi[(size_t)SB*H3];
__device__ __half g_hs[(size_t)SB*HID];
__device__ __half g_h16[2][BATCH*HID];
__device__ unsigned g_bar_count = 0;
__device__ volatile unsigned g_bar_sense = 0;

// ---------------- ptx helpers ----------------
__device__ __forceinline__ uint32_t smem_u32(const void* p){
    return (uint32_t)__cvta_generic_to_shared(p);
}
__device__ __forceinline__ void ldsm_x4(uint32_t&a0,uint32_t&a1,uint32_t&a2,uint32_t&a3,uint32_t addr){
    asm volatile("ldmatrix.sync.aligned.m8n8.x4.shared.b16 {%0,%1,%2,%3},[%4];"
                 :"=r"(a0),"=r"(a1),"=r"(a2),"=r"(a3):"r"(addr));
}
__device__ __forceinline__ void ldsm_x2(uint32_t&b0,uint32_t&b1,uint32_t addr){
    asm volatile("ldmatrix.sync.aligned.m8n8.x2.shared.b16 {%0,%1},[%2];"
                 :"=r"(b0),"=r"(b1):"r"(addr));
}
__device__ __forceinline__ void mma16816(float&d0,float&d1,float&d2,float&d3,
                                         uint32_t a0,uint32_t a1,uint32_t a2,uint32_t a3,
                                         uint32_t b0,uint32_t b1){
    asm volatile("mma.sync.aligned.m16n8k16.row.col.f32.f16.f16.f32 "
                 "{%0,%1,%2,%3},{%4,%5,%6,%7},{%8,%9},{%0,%1,%2,%3};"
                 :"+f"(d0),"+f"(d1),"+f"(d2),"+f"(d3)
                 :"r"(a0),"r"(a1),"r"(a2),"r"(a3),"r"(b0),"r"(b1));
}
__device__ __forceinline__ void cp16(uint32_t saddr, const void* g){
    asm volatile("cp.async.cg.shared.global [%0],[%1],16;"::"r"(saddr),"l"(g));
}
__device__ __forceinline__ void cp_commit(){ asm volatile("cp.async.commit_group;"); }
template<int N> __device__ __forceinline__ void cp_wait(){ asm volatile("cp.async.wait_group %0;"::"n"(N)); }

// ---------------- prep kernels ----------------
__global__ void k_cvt(const float* __restrict__ src, __half* __restrict__ dst, int n2){
    int i = blockIdx.x*blockDim.x + threadIdx.x;
    if (i < n2){
        float2 v = reinterpret_cast<const float2*>(src)[i];
        reinterpret_cast<__half2*>(dst)[i] = __floats2half2_rn(v.x, v.y);
    }
}
__global__ void k_embed(const int* __restrict__ x, const float* __restrict__ emb){
    int i = blockIdx.x*blockDim.x + threadIdx.x;
    if (i >= SB*EMBD/2) return;
    int row = i/(EMBD/2), cp = i%(EMBD/2);
    int s = row>>6, b = row&63;
    int tok = (s==0) ? 2 : x[(s-1)*BATCH + b];
    float2 v = reinterpret_cast<const float2*>(emb + (size_t)tok*EMBD)[cp];
    float a0 = (tok==0)?0.f:fmaxf(v.x,0.f);
    float a1 = (tok==0)?0.f:fmaxf(v.y,0.f);
    reinterpret_cast<__half2*>(g_E)[i] = __floats2half2_rn(a0, a1);
}
__global__ void k_inith(const float* __restrict__ hidden){
    int i = blockIdx.x*blockDim.x + threadIdx.x;
    if (i < BATCH*HID) g_h16[0][i] = __float2half(hidden[i]);
}

// ---------------- cp.async-fed HMMA GEMM: C(MxN) = A(MxK) @ Bw(NxK)^T + bias ----------------
// BM=128, BN=256, BK=64. 256 threads = 8 warps (2m x 4n), warp tile 64x64. 3-stage cp.async.
#define GBM 128
#define GBN 256
#define GBK 64
#define ROWB 144                     // 128B payload + 16B pad (conflict-free ldsm)
#define STG_ROWS (GBM+GBN)           // 384
#define STG_BYTES (STG_ROWS*ROWB)    // 55296
#define NSTAGE 3
#define G_SMEM (NSTAGE*STG_BYTES)    // 165888

template<bool PERMUTE>
__global__ __launch_bounds__(256,1)
void k_gemm(const __half* __restrict__ A, const __half* __restrict__ Bw,
            const float* __restrict__ bias, float* __restrict__ C, int K, int N){
    extern __shared__ char smem[];
    uint32_t sbase = smem_u32(smem);
    int tid = threadIdx.x;
    int bm = blockIdx.x, bn = blockIdx.y;   // x fast => B tile L2-shared by 32 consecutive CTAs
    const __half* Ab = A + (size_t)bm*GBM*K;
    const __half* Bb = Bw + (size_t)bn*GBN*K;

    int NK = K/GBK;
    // one stage = 384 rows x 128B = 3072 cp16 = 12 per thread
    auto load_stage = [&](int i){
        int s = i % NSTAGE;
        uint32_t stg = sbase + s*STG_BYTES;
        #pragma unroll
        for (int t=0;t<12;t++){
            int c = tid + t*256;          // 0..3071
            int row = c>>3, c16 = c&7;
            const __half* src = (row < GBM)
                ? (Ab + (size_t)row*K + i*GBK + c16*8)
                : (Bb + (size_t)(row-GBM)*K + i*GBK + c16*8);
            cp16(stg + row*ROWB + c16*16, src);
        }
        cp_commit();
    };
    load_stage(0); load_stage(1); load_stage(2);

    int warp = tid>>5, lane = tid&31;
    int wm = warp&1, wn = warp>>1;   // warp tile: m = wm*64, n = wn*64
    float acc[4][8][4];
    #pragma unroll
    for(int mi=0;mi<4;mi++) for(int ni=0;ni<8;ni++) for(int d=0;d<4;d++) acc[mi][ni][d]=0.f;

    for (int i=0; i<NK; i++){
        if      (i <= NK-3) cp_wait<2>();
        else if (i == NK-2) cp_wait<1>();
        else                cp_wait<0>();
        __syncthreads();
        uint32_t sA = sbase + (i%NSTAGE)*STG_BYTES;
        uint32_t sB = sA + GBM*ROWB;
        #pragma unroll
        for (int k16=0; k16<GBK/16; k16++){
            uint32_t a[4][4], b[4][4];
            #pragma unroll
            for(int mi=0;mi<4;mi++){
                int row = wm*64 + mi*16 + (lane&15);
                int col = (k16*16 + (lane>>4)*8)*2;
                ldsm_x4(a[mi][0],a[mi][1],a[mi][2],a[mi][3], sA + row*ROWB + col);
            }
            #pragma unroll
            for(int nj=0;nj<4;nj++){
                int row = wn*64 + nj*16 + ((lane>>4)*8) + (lane&7);
                int col = (k16*16 + ((lane>>3)&1)*8)*2;
                ldsm_x4(b[nj][0],b[nj][1],b[nj][2],b[nj][3], sB + row*ROWB + col);
            }
            #pragma unroll
            for(int mi=0;mi<4;mi++)
                #pragma unroll
                for(int nj=0;nj<4;nj++){
                    mma16816(acc[mi][2*nj][0],acc[mi][2*nj][1],acc[mi][2*nj][2],acc[mi][2*nj][3],
                             a[mi][0],a[mi][1],a[mi][2],a[mi][3], b[nj][0],b[nj][1]);
                    mma16816(acc[mi][2*nj+1][0],acc[mi][2*nj+1][1],acc[mi][2*nj+1][2],acc[mi][2*nj+1][3],
                             a[mi][0],a[mi][1],a[mi][2],a[mi][3], b[nj][2],b[nj][3]);
                }
        }
        __syncthreads();
        if (i + NSTAGE < NK) load_stage(i + NSTAGE);
    }

    int mbase = bm*GBM + wm*64;
    int nbase = bn*GBN + wn*64;
    #pragma unroll
    for(int mi=0;mi<4;mi++){
        int r0 = mbase + mi*16 + (lane>>2);
        #pragma unroll
        for(int ni=0;ni<8;ni++){
            int cc = nbase + ni*8 + 2*(lane&3);
            float bv0 = bias[cc], bv1 = bias[cc+1];
            int rr = r0;
            size_t ro = PERMUTE ? (size_t)((rr&63)*64 + (rr>>6))*N : (size_t)rr*N;
            *reinterpret_cast<float2*>(C + ro + cc) = make_float2(acc[mi][ni][0]+bv0, acc[mi][ni][1]+bv1);
            rr = r0+8;
            ro = PERMUTE ? (size_t)((rr&63)*64 + (rr>>6))*N : (size_t)rr*N;
            *reinterpret_cast<float2*>(C + ro + cc) = make_float2(acc[mi][ni][2]+bv0, acc[mi][ni][3]+bv1);
        }
    }
}

// ---------------- persistent recurrence (unchanged from R3, passing) ----------------
#define RC_CTAS 64
#define SW_STRIDE 1032
#define SH_STRIDE 264
#define RC_SMEM (48*SW_STRIDE*2 + 64*SH_STRIDE*2 + 64*48*4)

__global__ __launch_bounds__(256)
void k_recur(const float* __restrict__ w_hh, const float* __restrict__ b_hh,
             const float* __restrict__ hidden){
    extern __shared__ char smem[];
    __half* sW  = (__half*)smem;
    __half* sH  = (__half*)(smem + 48*SW_STRIDE*2);
    float*  sGH = (float*)(smem + 48*SW_STRIDE*2 + 64*SH_STRIDE*2);
    int tid = threadIdx.x, cta = blockIdx.x;
    int j0 = cta*16;

    for (int idx = tid; idx < 48*HID; idx += 256){
        int r = idx>>10, k = idx&1023;
        int g = r>>4, jr = r&15;
        sW[r*SW_STRIDE + k] = __float2half(w_hh[(size_t)(g*HID + j0 + jr)*HID + k]);
    }
    float bh0[4], bh1[4], bh2[4], hold[4];
    #pragma unroll
    for (int t=0;t<4;t++){
        int o = tid + t*256; int b = o>>4, jj = o&15; int j = j0+jj;
        bh0[t]=b_hh[j]; bh1[t]=b_hh[HID+j]; bh2[t]=b_hh[2*HID+j];
        hold[t]=hidden[b*HID + j];
    }
    int warp=tid>>5, lane=tid&31;
    int wm = warp&3, wn = warp>>2;
    __syncthreads();

    for (int s=0; s<SEQ; s++){
        const __half* hb = g_h16[s&1];
        float acc[3][4];
        #pragma unroll
        for(int ni=0;ni<3;ni++) for(int d=0;d<4;d++) acc[ni][d]=0.f;

        for (int ch=0; ch<4; ch++){
            __syncthreads();
            #pragma unroll
            for (int i=0;i<8;i++){
                int lin = tid + i*256;
                int row = lin>>5, c16 = lin&31;
                uint4 v = __ldcg(reinterpret_cast<const uint4*>(hb + row*HID + ch*256 + c16*8));
                *reinterpret_cast<uint4*>(&sH[row*SH_STRIDE + c16*8]) = v;
            }
            __syncthreads();
            #pragma unroll
            for (int k16=0;k16<16;k16++){
                uint32_t a0,a1,a2,a3;
                int arow = wm*16 + (lane&15);
                int acol = k16*16 + (lane>>4)*8;
                ldsm_x4(a0,a1,a2,a3, smem_u32(&sH[arow*SH_STRIDE + acol]));
                #pragma unroll
                for (int ni=0;ni<3;ni++){
                    uint32_t b0,b1;
                    int brow = wn*24 + ni*8 + (lane&7);
                    int bcol = ch*256 + k16*16 + ((lane>>3)&1)*8;
                    ldsm_x2(b0,b1, smem_u32(&sW[brow*SW_STRIDE + bcol]));
                    mma16816(acc[ni][0],acc[ni][1],acc[ni][2],acc[ni][3],a0,a1,a2,a3,b0,b1);
                }
            }
        }
        __syncthreads();
        {
            int r = wm*16 + (lane>>2);
            #pragma unroll
            for(int ni=0;ni<3;ni++){
                int cc = wn*24 + ni*8 + 2*(lane&3);
                sGH[r*48 + cc]       = acc[ni][0];
                sGH[r*48 + cc+1]     = acc[ni][1];
                sGH[(r+8)*48 + cc]   = acc[ni][2];
                sGH[(r+8)*48 + cc+1] = acc[ni][3];
            }
        }
        __syncthreads();
        __half* hwr = g_h16[(s+1)&1];
        #pragma unroll
        for (int t=0;t<4;t++){
            int o = tid + t*256; int b = o>>4, jj = o&15; int j = j0+jj;
            const float* gi = g_gi + (size_t)(s*BATCH + b)*H3;
            float ir = gi[j], iz = gi[HID+j], inn = gi[2*HID+j];
            float hr = sGH[b*48+jj]    + bh0[t];
            float hz = sGH[b*48+16+jj] + bh1[t];
            float hn = sGH[b*48+32+jj] + bh2[t];
            float rg = 1.f/(1.f+__expf(-(ir+hr)));
            float zg = 1.f/(1.f+__expf(-(iz+hz)));
            float ng = tanhf(inn + rg*hn);
            float hnew = (1.f - zg)*ng + zg*hold[t];
            hold[t] = hnew;
            unsigned short hb16 = __half_as_ushort(__float2half(hnew));
            __stcg(reinterpret_cast<unsigned short*>(hwr + b*HID + j), hb16);
            __stcg(reinterpret_cast<unsigned short*>(g_hs + (size_t)(s*BATCH + b)*HID + j), hb16);
        }
        if (s < SEQ-1){
            __threadfence();
            __syncthreads();
            if (tid==0){
                unsigned old = g_bar_sense;
                unsigned a = atomicAdd(&g_bar_count, 1u);
                if (a == RC_CTAS-1){
                    g_bar_count = 0;
                    __threadfence();
                    atomicExch((unsigned*)&g_bar_sense, old+1u);
                } else {
                    while (g_bar_sense == old) __nanosleep(32);
                }
                __threadfence();
            }
            __syncthreads();
        }
    }
}

// ---------------- launch ----------------
extern "C" void kernel_launch(void* const* d_in, const int* in_sizes, int n_in,
                              void* d_out, int out_size){
    const int*   x      = (const int*)  d_in[0];
    const float* hidden = (const float*)d_in[1];
    const float* emb    = (const float*)d_in[2];
    const float* w_ih   = (const float*)d_in[3];
    const float* w_hh   = (const float*)d_in[4];
    const float* b_ih   = (const float*)d_in[5];
    const float* b_hh   = (const float*)d_in[6];
    const float* w_out  = (const float*)d_in[7];
    const float* b_out  = (const float*)d_in[8];
    float* out = (float*)d_out;

    __half *pE, *pWih, *pWout, *pHs;
    float  *pGi;
    cudaGetSymbolAddress((void**)&pE,    g_E);
    cudaGetSymbolAddress((void**)&pWih,  g_wih);
    cudaGetSymbolAddress((void**)&pWout, g_wout);
    cudaGetSymbolAddress((void**)&pGi,   g_gi);
    cudaGetSymbolAddress((void**)&pHs,   g_hs);

    cudaFuncSetAttribute(k_recur, cudaFuncAttributeMaxDynamicSharedMemorySize, RC_SMEM);
    cudaFuncSetAttribute(k_gemm<false>, cudaFuncAttributeMaxDynamicSharedMemorySize, G_SMEM);
    cudaFuncSetAttribute(k_gemm<true>,  cudaFuncAttributeMaxDynamicSharedMemorySize, G_SMEM);

    {   int n2 = (int)((size_t)VOCAB*HID/2);
        k_cvt<<<(n2+255)/256,256>>>(w_out, pWout, n2); }
    {   int n2 = H3*EMBD/2;
        k_cvt<<<(n2+255)/256,256>>>(w_ih, pWih, n2); }
    k_embed<<<(SB*EMBD/2+255)/256,256>>>(x, emb);
    k_inith<<<(BATCH*HID+255)/256,256>>>(hidden);

    // gi = relu(E) @ w_ih^T + b_ih   (4096 x 3072, K=512)
    k_gemm<false><<<dim3(SB/GBM, H3/GBN), 256, G_SMEM>>>(pE, pWih, b_ih, pGi, EMBD, H3);

    // sequential GRU
    k_recur<<<RC_CTAS, 256, RC_SMEM>>>(w_hh, b_hh, hidden);

    // logits = hs @ w_out^T + b_out, rows permuted (s,b) -> (b,s)
    k_gemm<true><<<dim3(SB/GBM, VOCAB/GBN), 256, G_SMEM>>>(pHs, pWout, b_out, out, HID, VOCAB);
}

// round 8
// speedup vs baseline: 1.0571x; 1.0003x over previous
#include <cuda_runtime.h>
#include <cuda_fp16.h>
#include <cstdint>

#define SEQ   64
#define BATCH 64
#define EMBD  512
#define HID   1024
#define VOCAB 32000
#define SB    (SEQ*BATCH)
#define H3    (3*HID)

// ---------------- device scratch (no cudaMalloc allowed) ----------------
__device__ __half g_E[SB*EMBD];
__device__ __half g_wih[H3*EMBD];
__device__ __half g_wout[(size_t)VOCAB*HID];
__device__ float  g_gi[(size_t)SB*H3];
__device__ __half g_hs[(size_t)SB*HID];
__device__ __half g_h16[2][BATCH*HID];
__device__ unsigned g_bar_count = 0;
__device__ volatile unsigned g_bar_sense = 0;

// ---------------- ptx helpers ----------------
__device__ __forceinline__ uint32_t smem_u32(const void* p){
    return (uint32_t)__cvta_generic_to_shared(p);
}
__device__ __forceinline__ void ldsm_x4(uint32_t&a0,uint32_t&a1,uint32_t&a2,uint32_t&a3,uint32_t addr){
    asm volatile("ldmatrix.sync.aligned.m8n8.x4.shared.b16 {%0,%1,%2,%3},[%4];"
                 :"=r"(a0),"=r"(a1),"=r"(a2),"=r"(a3):"r"(addr));
}
__device__ __forceinline__ void ldsm_x2(uint32_t&b0,uint32_t&b1,uint32_t addr){
    asm volatile("ldmatrix.sync.aligned.m8n8.x2.shared.b16 {%0,%1},[%2];"
                 :"=r"(b0),"=r"(b1):"r"(addr));
}
__device__ __forceinline__ void mma16816(float&d0,float&d1,float&d2,float&d3,
                                         uint32_t a0,uint32_t a1,uint32_t a2,uint32_t a3,
                                         uint32_t b0,uint32_t b1){
    asm volatile("mma.sync.aligned.m16n8k16.row.col.f32.f16.f16.f32 "
                 "{%0,%1,%2,%3},{%4,%5,%6,%7},{%8,%9},{%0,%1,%2,%3};"
                 :"+f"(d0),"+f"(d1),"+f"(d2),"+f"(d3)
                 :"r"(a0),"r"(a1),"r"(a2),"r"(a3),"r"(b0),"r"(b1));
}
__device__ __forceinline__ void cp16(uint32_t saddr, const void* g){
    asm volatile("cp.async.cg.shared.global [%0],[%1],16;"::"r"(saddr),"l"(g));
}
__device__ __forceinline__ void cp_commit(){ asm volatile("cp.async.commit_group;"); }
template<int N> __device__ __forceinline__ void cp_wait(){ asm volatile("cp.async.wait_group %0;"::"n"(N)); }

// ---------------- prep kernels ----------------
__global__ void k_cvt(const float* __restrict__ src, __half* __restrict__ dst, int n2){
    int i = blockIdx.x*blockDim.x + threadIdx.x;
    if (i < n2){
        float2 v = reinterpret_cast<const float2*>(src)[i];
        reinterpret_cast<__half2*>(dst)[i] = __floats2half2_rn(v.x, v.y);
    }
}
__global__ void k_embed(const int* __restrict__ x, const float* __restrict__ emb){
    int i = blockIdx.x*blockDim.x + threadIdx.x;
    if (i >= SB*EMBD/2) return;
    int row = i/(EMBD/2), cp = i%(EMBD/2);
    int s = row>>6, b = row&63;
    int tok = (s==0) ? 2 : x[(s-1)*BATCH + b];
    float2 v = reinterpret_cast<const float2*>(emb + (size_t)tok*EMBD)[cp];
    float a0 = (tok==0)?0.f:fmaxf(v.x,0.f);
    float a1 = (tok==0)?0.f:fmaxf(v.y,0.f);
    reinterpret_cast<__half2*>(g_E)[i] = __floats2half2_rn(a0, a1);
}
__global__ void k_inith(const float* __restrict__ hidden){
    int i = blockIdx.x*blockDim.x + threadIdx.x;
    if (i < BATCH*HID) g_h16[0][i] = __float2half(hidden[i]);
}

// ---------------- cp.async-fed HMMA GEMM: C(MxN) = A(MxK) @ Bw(NxK)^T + bias ----------------
// BM=128, BN=256, BK=64. 512 threads = 16 warps (4m x 4n), warp tile 32x64.
// 4 warps/SMSP for latency hiding of synchronous mma. 3-stage cp.async.
#define GBM 128
#define GBN 256
#define GBK 64
#define ROWB 144                     // 128B payload + 16B pad (conflict-free ldsm)
#define STG_ROWS (GBM+GBN)           // 384
#define STG_BYTES (STG_ROWS*ROWB)    // 55296
#define NSTAGE 3
#define G_SMEM (NSTAGE*STG_BYTES)    // 165888
#define GTHREADS 512

template<bool PERMUTE>
__global__ __launch_bounds__(GTHREADS,1)
void k_gemm(const __half* __restrict__ A, const __half* __restrict__ Bw,
            const float* __restrict__ bias, float* __restrict__ C, int K, int N){
    extern __shared__ char smem[];
    uint32_t sbase = smem_u32(smem);
    int tid = threadIdx.x;
    int bm = blockIdx.x, bn = blockIdx.y;   // x fast => B tile L2-shared by 32 consecutive CTAs
    const __half* Ab = A + (size_t)bm*GBM*K;
    const __half* Bb = Bw + (size_t)bn*GBN*K;

    int NK = K/GBK;
    // one stage = 384 rows x 128B = 3072 cp16 = 6 per thread
    auto load_stage = [&](int i){
        int s = i % NSTAGE;
        uint32_t stg = sbase + s*STG_BYTES;
        #pragma unroll
        for (int t=0;t<6;t++){
            int c = tid + t*GTHREADS;     // 0..3071
            int row = c>>3, c16 = c&7;
            const __half* src = (row < GBM)
                ? (Ab + (size_t)row*K + i*GBK + c16*8)
                : (Bb + (size_t)(row-GBM)*K + i*GBK + c16*8);
            cp16(stg + row*ROWB + c16*16, src);
        }
        cp_commit();
    };
    load_stage(0); load_stage(1); load_stage(2);

    int warp = tid>>5, lane = tid&31;
    int wm = warp&3, wn = warp>>2;   // warp tile: m = wm*32, n = wn*64
    float acc[2][8][4];
    #pragma unroll
    for(int mi=0;mi<2;mi++) for(int ni=0;ni<8;ni++) for(int d=0;d<4;d++) acc[mi][ni][d]=0.f;

    for (int i=0; i<NK; i++){
        if      (i <= NK-3) cp_wait<2>();
        else if (i == NK-2) cp_wait<1>();
        else                cp_wait<0>();
        __syncthreads();
        uint32_t sA = sbase + (i%NSTAGE)*STG_BYTES;
        uint32_t sB = sA + GBM*ROWB;
        #pragma unroll
        for (int k16=0; k16<GBK/16; k16++){
            uint32_t a[2][4], b[4][4];
            #pragma unroll
            for(int mi=0;mi<2;mi++){
                int row = wm*32 + mi*16 + (lane&15);
                int col = (k16*16 + (lane>>4)*8)*2;
                ldsm_x4(a[mi][0],a[mi][1],a[mi][2],a[mi][3], sA + row*ROWB + col);
            }
            #pragma unroll
            for(int nj=0;nj<4;nj++){
                int row = wn*64 + nj*16 + ((lane>>4)*8) + (lane&7);
                int col = (k16*16 + ((lane>>3)&1)*8)*2;
                ldsm_x4(b[nj][0],b[nj][1],b[nj][2],b[nj][3], sB + row*ROWB + col);
            }
            #pragma unroll
            for(int mi=0;mi<2;mi++)
                #pragma unroll
                for(int nj=0;nj<4;nj++){
                    mma16816(acc[mi][2*nj][0],acc[mi][2*nj][1],acc[mi][2*nj][2],acc[mi][2*nj][3],
                             a[mi][0],a[mi][1],a[mi][2],a[mi][3], b[nj][0],b[nj][1]);
                    mma16816(acc[mi][2*nj+1][0],acc[mi][2*nj+1][1],acc[mi][2*nj+1][2],acc[mi][2*nj+1][3],
                             a[mi][0],a[mi][1],a[mi][2],a[mi][3], b[nj][2],b[nj][3]);
                }
        }
        __syncthreads();
        if (i + NSTAGE < NK) load_stage(i + NSTAGE);
    }

    int mbase = bm*GBM + wm*32;
    int nbase = bn*GBN + wn*64;
    #pragma unroll
    for(int mi=0;mi<2;mi++){
        int r0 = mbase + mi*16 + (lane>>2);
        #pragma unroll
        for(int ni=0;ni<8;ni++){
            int cc = nbase + ni*8 + 2*(lane&3);
            float bv0 = bias[cc], bv1 = bias[cc+1];
            int rr = r0;
            size_t ro = PERMUTE ? (size_t)((rr&63)*64 + (rr>>6))*N : (size_t)rr*N;
            *reinterpret_cast<float2*>(C + ro + cc) = make_float2(acc[mi][ni][0]+bv0, acc[mi][ni][1]+bv1);
            rr = r0+8;
            ro = PERMUTE ? (size_t)((rr&63)*64 + (rr>>6))*N : (size_t)rr*N;
            *reinterpret_cast<float2*>(C + ro + cc) = make_float2(acc[mi][ni][2]+bv0, acc[mi][ni][3]+bv1);
        }
    }
}

// ---------------- persistent recurrence (unchanged, passing) ----------------
#define RC_CTAS 64
#define SW_STRIDE 1032
#define SH_STRIDE 264
#define RC_SMEM (48*SW_STRIDE*2 + 64*SH_STRIDE*2 + 64*48*4)

__global__ __launch_bounds__(256)
void k_recur(const float* __restrict__ w_hh, const float* __restrict__ b_hh,
             const float* __restrict__ hidden){
    extern __shared__ char smem[];
    __half* sW  = (__half*)smem;
    __half* sH  = (__half*)(smem + 48*SW_STRIDE*2);
    float*  sGH = (float*)(smem + 48*SW_STRIDE*2 + 64*SH_STRIDE*2);
    int tid = threadIdx.x, cta = blockIdx.x;
    int j0 = cta*16;

    for (int idx = tid; idx < 48*HID; idx += 256){
        int r = idx>>10, k = idx&1023;
        int g = r>>4, jr = r&15;
        sW[r*SW_STRIDE + k] = __float2half(w_hh[(size_t)(g*HID + j0 + jr)*HID + k]);
    }
    float bh0[4], bh1[4], bh2[4], hold[4];
    #pragma unroll
    for (int t=0;t<4;t++){
        int o = tid + t*256; int b = o>>4, jj = o&15; int j = j0+jj;
        bh0[t]=b_hh[j]; bh1[t]=b_hh[HID+j]; bh2[t]=b_hh[2*HID+j];
        hold[t]=hidden[b*HID + j];
    }
    int warp=tid>>5, lane=tid&31;
    int wm = warp&3, wn = warp>>2;
    __syncthreads();

    for (int s=0; s<SEQ; s++){
        const __half* hb = g_h16[s&1];
        float acc[3][4];
        #pragma unroll
        for(int ni=0;ni<3;ni++) for(int d=0;d<4;d++) acc[ni][d]=0.f;

        for (int ch=0; ch<4; ch++){
            __syncthreads();
            #pragma unroll
            for (int i=0;i<8;i++){
                int lin = tid + i*256;
                int row = lin>>5, c16 = lin&31;
                uint4 v = __ldcg(reinterpret_cast<const uint4*>(hb + row*HID + ch*256 + c16*8));
                *reinterpret_cast<uint4*>(&sH[row*SH_STRIDE + c16*8]) = v;
            }
            __syncthreads();
            #pragma unroll
            for (int k16=0;k16<16;k16++){
                uint32_t a0,a1,a2,a3;
                int arow = wm*16 + (lane&15);
                int acol = k16*16 + (lane>>4)*8;
                ldsm_x4(a0,a1,a2,a3, smem_u32(&sH[arow*SH_STRIDE + acol]));
                #pragma unroll
                for (int ni=0;ni<3;ni++){
                    uint32_t b0,b1;
                    int brow = wn*24 + ni*8 + (lane&7);
                    int bcol = ch*256 + k16*16 + ((lane>>3)&1)*8;
                    ldsm_x2(b0,b1, smem_u32(&sW[brow*SW_STRIDE + bcol]));
                    mma16816(acc[ni][0],acc[ni][1],acc[ni][2],acc[ni][3],a0,a1,a2,a3,b0,b1);
                }
            }
        }
        __syncthreads();
        {
            int r = wm*16 + (lane>>2);
            #pragma unroll
            for(int ni=0;ni<3;ni++){
                int cc = wn*24 + ni*8 + 2*(lane&3);
                sGH[r*48 + cc]       = acc[ni][0];
                sGH[r*48 + cc+1]     = acc[ni][1];
                sGH[(r+8)*48 + cc]   = acc[ni][2];
                sGH[(r+8)*48 + cc+1] = acc[ni][3];
            }
        }
        __syncthreads();
        __half* hwr = g_h16[(s+1)&1];
        #pragma unroll
        for (int t=0;t<4;t++){
            int o = tid + t*256; int b = o>>4, jj = o&15; int j = j0+jj;
            const float* gi = g_gi + (size_t)(s*BATCH + b)*H3;
            float ir = gi[j], iz = gi[HID+j], inn = gi[2*HID+j];
            float hr = sGH[b*48+jj]    + bh0[t];
            float hz = sGH[b*48+16+jj] + bh1[t];
            float hn = sGH[b*48+32+jj] + bh2[t];
            float rg = 1.f/(1.f+__expf(-(ir+hr)));
            float zg = 1.f/(1.f+__expf(-(iz+hz)));
            float ng = tanhf(inn + rg*hn);
            float hnew = (1.f - zg)*ng + zg*hold[t];
            hold[t] = hnew;
            unsigned short hb16 = __half_as_ushort(__float2half(hnew));
            __stcg(reinterpret_cast<unsigned short*>(hwr + b*HID + j), hb16);
            __stcg(reinterpret_cast<unsigned short*>(g_hs + (size_t)(s*BATCH + b)*HID + j), hb16);
        }
        if (s < SEQ-1){
            __threadfence();
            __syncthreads();
            if (tid==0){
                unsigned old = g_bar_sense;
                unsigned a = atomicAdd(&g_bar_count, 1u);
                if (a == RC_CTAS-1){
                    g_bar_count = 0;
                    __threadfence();
                    atomicExch((unsigned*)&g_bar_sense, old+1u);
                } else {
                    while (g_bar_sense == old) __nanosleep(32);
                }
                __threadfence();
            }
            __syncthreads();
        }
    }
}

// ---------------- launch ----------------
extern "C" void kernel_launch(void* const* d_in, const int* in_sizes, int n_in,
                              void* d_out, int out_size){
    const int*   x      = (const int*)  d_in[0];
    const float* hidden = (const float*)d_in[1];
    const float* emb    = (const float*)d_in[2];
    const float* w_ih   = (const float*)d_in[3];
    const float* w_hh   = (const float*)d_in[4];
    const float* b_ih   = (const float*)d_in[5];
    const float* b_hh   = (const float*)d_in[6];
    const float* w_out  = (const float*)d_in[7];
    const float* b_out  = (const float*)d_in[8];
    float* out = (float*)d_out;

    __half *pE, *pWih, *pWout, *pHs;
    float  *pGi;
    cudaGetSymbolAddress((void**)&pE,    g_E);
    cudaGetSymbolAddress((void**)&pWih,  g_wih);
    cudaGetSymbolAddress((void**)&pWout, g_wout);
    cudaGetSymbolAddress((void**)&pGi,   g_gi);
    cudaGetSymbolAddress((void**)&pHs,   g_hs);

    cudaFuncSetAttribute(k_recur, cudaFuncAttributeMaxDynamicSharedMemorySize, RC_SMEM);
    cudaFuncSetAttribute(k_gemm<false>, cudaFuncAttributeMaxDynamicSharedMemorySize, G_SMEM);
    cudaFuncSetAttribute(k_gemm<true>,  cudaFuncAttributeMaxDynamicSharedMemorySize, G_SMEM);

    {   int n2 = (int)((size_t)VOCAB*HID/2);
        k_cvt<<<(n2+255)/256,256>>>(w_out, pWout, n2); }
    {   int n2 = H3*EMBD/2;
        k_cvt<<<(n2+255)/256,256>>>(w_ih, pWih, n2); }
    k_embed<<<(SB*EMBD/2+255)/256,256>>>(x, emb);
    k_inith<<<(BATCH*HID+255)/256,256>>>(hidden);

    // gi = relu(E) @ w_ih^T + b_ih   (4096 x 3072, K=512)
    k_gemm<false><<<dim3(SB/GBM, H3/GBN), GTHREADS, G_SMEM>>>(pE, pWih, b_ih, pGi, EMBD, H3);

    // sequential GRU
    k_recur<<<RC_CTAS, 256, RC_SMEM>>>(w_hh, b_hh, hidden);

    // logits = hs @ w_out^T + b_out, rows permuted (s,b) -> (b,s)
    k_gemm<true><<<dim3(SB/GBM, VOCAB/GBN), GTHREADS, G_SMEM>>>(pHs, pWout, b_out, out, HID, VOCAB);
}

// round 9
// speedup vs baseline: 1.1232x; 1.0625x over previous
#include <cuda_runtime.h>
#include <cuda_fp16.h>
#include <cstdint>

#define SEQ   64
#define BATCH 64
#define EMBD  512
#define HID   1024
#define VOCAB 32000
#define SB    (SEQ*BATCH)
#define H3    (3*HID)

// ---------------- device scratch (no cudaMalloc allowed) ----------------
__device__ __half g_E[SB*EMBD];
__device__ __half g_wih[H3*EMBD];
__device__ __half g_wout[(size_t)VOCAB*HID];
__device__ float  g_gi[(size_t)SB*H3];
__device__ __half g_hs[(size_t)SB*HID];
__device__ __half g_h16[2][BATCH*HID];
__device__ unsigned g_bar_count = 0;
__device__ volatile unsigned g_bar_sense = 0;

// ---------------- ptx helpers ----------------
__device__ __forceinline__ uint32_t smem_u32(const void* p){
    return (uint32_t)__cvta_generic_to_shared(p);
}
__device__ __forceinline__ void ldsm_x4(uint32_t&a0,uint32_t&a1,uint32_t&a2,uint32_t&a3,uint32_t addr){
    asm volatile("ldmatrix.sync.aligned.m8n8.x4.shared.b16 {%0,%1,%2,%3},[%4];"
                 :"=r"(a0),"=r"(a1),"=r"(a2),"=r"(a3):"r"(addr));
}
__device__ __forceinline__ void ldsm_x2(uint32_t&b0,uint32_t&b1,uint32_t addr){
    asm volatile("ldmatrix.sync.aligned.m8n8.x2.shared.b16 {%0,%1},[%2];"
                 :"=r"(b0),"=r"(b1):"r"(addr));
}
__device__ __forceinline__ void mma16816(float&d0,float&d1,float&d2,float&d3,
                                         uint32_t a0,uint32_t a1,uint32_t a2,uint32_t a3,
                                         uint32_t b0,uint32_t b1){
    asm volatile("mma.sync.aligned.m16n8k16.row.col.f32.f16.f16.f32 "
                 "{%0,%1,%2,%3},{%4,%5,%6,%7},{%8,%9},{%0,%1,%2,%3};"
                 :"+f"(d0),"+f"(d1),"+f"(d2),"+f"(d3)
                 :"r"(a0),"r"(a1),"r"(a2),"r"(a3),"r"(b0),"r"(b1));
}
__device__ __forceinline__ void cp16(uint32_t saddr, const void* g){
    asm volatile("cp.async.cg.shared.global [%0],[%1],16;"::"r"(saddr),"l"(g));
}
__device__ __forceinline__ void cp_commit(){ asm volatile("cp.async.commit_group;"); }
template<int N> __device__ __forceinline__ void cp_wait(){ asm volatile("cp.async.wait_group %0;"::"n"(N)); }

// ---------------- prep kernels ----------------
__global__ void k_cvt(const float* __restrict__ src, __half* __restrict__ dst, int n2){
    int i = blockIdx.x*blockDim.x + threadIdx.x;
    if (i < n2){
        float2 v = reinterpret_cast<const float2*>(src)[i];
        reinterpret_cast<__half2*>(dst)[i] = __floats2half2_rn(v.x, v.y);
    }
}
__global__ void k_embed(const int* __restrict__ x, const float* __restrict__ emb){
    int i = blockIdx.x*blockDim.x + threadIdx.x;
    if (i >= SB*EMBD/2) return;
    int row = i/(EMBD/2), cp = i%(EMBD/2);
    int s = row>>6, b = row&63;
    int tok = (s==0) ? 2 : x[(s-1)*BATCH + b];
    float2 v = reinterpret_cast<const float2*>(emb + (size_t)tok*EMBD)[cp];
    float a0 = (tok==0)?0.f:fmaxf(v.x,0.f);
    float a1 = (tok==0)?0.f:fmaxf(v.y,0.f);
    reinterpret_cast<__half2*>(g_E)[i] = __floats2half2_rn(a0, a1);
}
__global__ void k_inith(const float* __restrict__ hidden){
    int i = blockIdx.x*blockDim.x + threadIdx.x;
    if (i < BATCH*HID) g_h16[0][i] = __float2half(hidden[i]);
}

// ---------------- cp.async-fed HMMA GEMM: C(MxN) = A(MxK) @ Bw(NxK)^T + bias ----------------
// BM=128, BN=128, BK=64. 256 threads = 8 warps (2m x 4n), warp tile 64x32.
// 2-stage, 74KB smem -> 2 CTAs/SM for cross-CTA bubble hiding.
#define GBM 128
#define GBN 128
#define GBK 64
#define ROWB 144                     // 128B payload + 16B pad (conflict-free ldsm)
#define STG_ROWS (GBM+GBN)           // 256
#define STG_BYTES (STG_ROWS*ROWB)    // 36864
#define NSTAGE 2
#define G_SMEM (NSTAGE*STG_BYTES)    // 73728

template<bool PERMUTE>
__global__ __launch_bounds__(256,2)
void k_gemm(const __half* __restrict__ A, const __half* __restrict__ Bw,
            const float* __restrict__ bias, float* __restrict__ C, int K, int N){
    extern __shared__ char smem[];
    uint32_t sbase = smem_u32(smem);
    int tid = threadIdx.x;
    int bm = blockIdx.x, bn = blockIdx.y;   // x fast => B tile L2-shared by 32 consecutive CTAs
    const __half* Ab = A + (size_t)bm*GBM*K;
    const __half* Bb = Bw + (size_t)bn*GBN*K;

    int NK = K/GBK;
    // one stage = 256 rows x 128B = 2048 cp16 = 8 per thread
    auto load_stage = [&](int i){
        uint32_t stg = sbase + (i&1)*STG_BYTES;
        #pragma unroll
        for (int t=0;t<8;t++){
            int c = tid + t*256;          // 0..2047
            int row = c>>3, c16 = c&7;
            const __half* src = (row < GBM)
                ? (Ab + (size_t)row*K + i*GBK + c16*8)
                : (Bb + (size_t)(row-GBM)*K + i*GBK + c16*8);
            cp16(stg + row*ROWB + c16*16, src);
        }
        cp_commit();
    };
    load_stage(0); load_stage(1);

    int warp = tid>>5, lane = tid&31;
    int wm = warp&1, wn = warp>>1;   // warp tile: m = wm*64, n = wn*32
    float acc[4][4][4];
    #pragma unroll
    for(int mi=0;mi<4;mi++) for(int ni=0;ni<4;ni++) for(int d=0;d<4;d++) acc[mi][ni][d]=0.f;

    for (int i=0; i<NK; i++){
        if (i <= NK-2) cp_wait<1>(); else cp_wait<0>();
        __syncthreads();
        uint32_t sA = sbase + (i&1)*STG_BYTES;
        uint32_t sB = sA + GBM*ROWB;
        #pragma unroll
        for (int k16=0; k16<GBK/16; k16++){
            uint32_t a[4][4], b[2][4];
            #pragma unroll
            for(int mi=0;mi<4;mi++){
                int row = wm*64 + mi*16 + (lane&15);
                int col = (k16*16 + (lane>>4)*8)*2;
                ldsm_x4(a[mi][0],a[mi][1],a[mi][2],a[mi][3], sA + row*ROWB + col);
            }
            #pragma unroll
            for(int nj=0;nj<2;nj++){
                int row = wn*32 + nj*16 + ((lane>>4)*8) + (lane&7);
                int col = (k16*16 + ((lane>>3)&1)*8)*2;
                ldsm_x4(b[nj][0],b[nj][1],b[nj][2],b[nj][3], sB + row*ROWB + col);
            }
            #pragma unroll
            for(int mi=0;mi<4;mi++)
                #pragma unroll
                for(int nj=0;nj<2;nj++){
                    mma16816(acc[mi][2*nj][0],acc[mi][2*nj][1],acc[mi][2*nj][2],acc[mi][2*nj][3],
                             a[mi][0],a[mi][1],a[mi][2],a[mi][3], b[nj][0],b[nj][1]);
                    mma16816(acc[mi][2*nj+1][0],acc[mi][2*nj+1][1],acc[mi][2*nj+1][2],acc[mi][2*nj+1][3],
                             a[mi][0],a[mi][1],a[mi][2],a[mi][3], b[nj][2],b[nj][3]);
                }
        }
        __syncthreads();
        if (i + NSTAGE < NK) load_stage(i + NSTAGE);
    }

    int mbase = bm*GBM + wm*64;
    int nbase = bn*GBN + wn*32;
    #pragma unroll
    for(int mi=0;mi<4;mi++){
        int r0 = mbase + mi*16 + (lane>>2);
        #pragma unroll
        for(int ni=0;ni<4;ni++){
            int cc = nbase + ni*8 + 2*(lane&3);
            float bv0 = bias[cc], bv1 = bias[cc+1];
            int rr = r0;
            size_t ro = PERMUTE ? (size_t)((rr&63)*64 + (rr>>6))*N : (size_t)rr*N;
            *reinterpret_cast<float2*>(C + ro + cc) = make_float2(acc[mi][ni][0]+bv0, acc[mi][ni][1]+bv1);
            rr = r0+8;
            ro = PERMUTE ? (size_t)((rr&63)*64 + (rr>>6))*N : (size_t)rr*N;
            *reinterpret_cast<float2*>(C + ro + cc) = make_float2(acc[mi][ni][2]+bv0, acc[mi][ni][3]+bv1);
        }
    }
}

// ---------------- persistent recurrence (unchanged, passing) ----------------
#define RC_CTAS 64
#define SW_STRIDE 1032
#define SH_STRIDE 264
#define RC_SMEM (48*SW_STRIDE*2 + 64*SH_STRIDE*2 + 64*48*4)

__global__ __launch_bounds__(256)
void k_recur(const float* __restrict__ w_hh, const float* __restrict__ b_hh,
             const float* __restrict__ hidden){
    extern __shared__ char smem[];
    __half* sW  = (__half*)smem;
    __half* sH  = (__half*)(smem + 48*SW_STRIDE*2);
    float*  sGH = (float*)(smem + 48*SW_STRIDE*2 + 64*SH_STRIDE*2);
    int tid = threadIdx.x, cta = blockIdx.x;
    int j0 = cta*16;

    for (int idx = tid; idx < 48*HID; idx += 256){
        int r = idx>>10, k = idx&1023;
        int g = r>>4, jr = r&15;
        sW[r*SW_STRIDE + k] = __float2half(w_hh[(size_t)(g*HID + j0 + jr)*HID + k]);
    }
    float bh0[4], bh1[4], bh2[4], hold[4];
    #pragma unroll
    for (int t=0;t<4;t++){
        int o = tid + t*256; int b = o>>4, jj = o&15; int j = j0+jj;
        bh0[t]=b_hh[j]; bh1[t]=b_hh[HID+j]; bh2[t]=b_hh[2*HID+j];
        hold[t]=hidden[b*HID + j];
    }
    int warp=tid>>5, lane=tid&31;
    int wm = warp&3, wn = warp>>2;
    __syncthreads();

    for (int s=0; s<SEQ; s++){
        const __half* hb = g_h16[s&1];
        float acc[3][4];
        #pragma unroll
        for(int ni=0;ni<3;ni++) for(int d=0;d<4;d++) acc[ni][d]=0.f;

        for (int ch=0; ch<4; ch++){
            __syncthreads();
            #pragma unroll
            for (int i=0;i<8;i++){
                int lin = tid + i*256;
                int row = lin>>5, c16 = lin&31;
                uint4 v = __ldcg(reinterpret_cast<const uint4*>(hb + row*HID + ch*256 + c16*8));
                *reinterpret_cast<uint4*>(&sH[row*SH_STRIDE + c16*8]) = v;
            }
            __syncthreads();
            #pragma unroll
            for (int k16=0;k16<16;k16++){
                uint32_t a0,a1,a2,a3;
                int arow = wm*16 + (lane&15);
                int acol = k16*16 + (lane>>4)*8;
                ldsm_x4(a0,a1,a2,a3, smem_u32(&sH[arow*SH_STRIDE + acol]));
                #pragma unroll
                for (int ni=0;ni<3;ni++){
                    uint32_t b0,b1;
                    int brow = wn*24 + ni*8 + (lane&7);
                    int bcol = ch*256 + k16*16 + ((lane>>3)&1)*8;
                    ldsm_x2(b0,b1, smem_u32(&sW[brow*SW_STRIDE + bcol]));
                    mma16816(acc[ni][0],acc[ni][1],acc[ni][2],acc[ni][3],a0,a1,a2,a3,b0,b1);
                }
            }
        }
        __syncthreads();
        {
            int r = wm*16 + (lane>>2);
            #pragma unroll
            for(int ni=0;ni<3;ni++){
                int cc = wn*24 + ni*8 + 2*(lane&3);
                sGH[r*48 + cc]       = acc[ni][0];
                sGH[r*48 + cc+1]     = acc[ni][1];
                sGH[(r+8)*48 + cc]   = acc[ni][2];
                sGH[(r+8)*48 + cc+1] = acc[ni][3];
            }
        }
        __syncthreads();
        __half* hwr = g_h16[(s+1)&1];
        #pragma unroll
        for (int t=0;t<4;t++){
            int o = tid + t*256; int b = o>>4, jj = o&15; int j = j0+jj;
            const float* gi = g_gi + (size_t)(s*BATCH + b)*H3;
            float ir = gi[j], iz = gi[HID+j], inn = gi[2*HID+j];
            float hr = sGH[b*48+jj]    + bh0[t];
            float hz = sGH[b*48+16+jj] + bh1[t];
            float hn = sGH[b*48+32+jj] + bh2[t];
            float rg = 1.f/(1.f+__expf(-(ir+hr)));
            float zg = 1.f/(1.f+__expf(-(iz+hz)));
            float ng = tanhf(inn + rg*hn);
            float hnew = (1.f - zg)*ng + zg*hold[t];
            hold[t] = hnew;
            unsigned short hb16 = __half_as_ushort(__float2half(hnew));
            __stcg(reinterpret_cast<unsigned short*>(hwr + b*HID + j), hb16);
            __stcg(reinterpret_cast<unsigned short*>(g_hs + (size_t)(s*BATCH + b)*HID + j), hb16);
        }
        if (s < SEQ-1){
            __threadfence();
            __syncthreads();
            if (tid==0){
                unsigned old = g_bar_sense;
                unsigned a = atomicAdd(&g_bar_count, 1u);
                if (a == RC_CTAS-1){
                    g_bar_count = 0;
                    __threadfence();
                    atomicExch((unsigned*)&g_bar_sense, old+1u);
                } else {
                    while (g_bar_sense == old) __nanosleep(32);
                }
                __threadfence();
            }
            __syncthreads();
        }
    }
}

// ---------------- launch ----------------
extern "C" void kernel_launch(void* const* d_in, const int* in_sizes, int n_in,
                              void* d_out, int out_size){
    const int*   x      = (const int*)  d_in[0];
    const float* hidden = (const float*)d_in[1];
    const float* emb    = (const float*)d_in[2];
    const float* w_ih   = (const float*)d_in[3];
    const float* w_hh   = (const float*)d_in[4];
    const float* b_ih   = (const float*)d_in[5];
    const float* b_hh   = (const float*)d_in[6];
    const float* w_out  = (const float*)d_in[7];
    const float* b_out  = (const float*)d_in[8];
    float* out = (float*)d_out;

    __half *pE, *pWih, *pWout, *pHs;
    float  *pGi;
    cudaGetSymbolAddress((void**)&pE,    g_E);
    cudaGetSymbolAddress((void**)&pWih,  g_wih);
    cudaGetSymbolAddress((void**)&pWout, g_wout);
    cudaGetSymbolAddress((void**)&pGi,   g_gi);
    cudaGetSymbolAddress((void**)&pHs,   g_hs);

    cudaFuncSetAttribute(k_recur, cudaFuncAttributeMaxDynamicSharedMemorySize, RC_SMEM);
    cudaFuncSetAttribute(k_gemm<false>, cudaFuncAttributeMaxDynamicSharedMemorySize, G_SMEM);
    cudaFuncSetAttribute(k_gemm<true>,  cudaFuncAttributeMaxDynamicSharedMemorySize, G_SMEM);

    {   int n2 = (int)((size_t)VOCAB*HID/2);
        k_cvt<<<(n2+255)/256,256>>>(w_out, pWout, n2); }
    {   int n2 = H3*EMBD/2;
        k_cvt<<<(n2+255)/256,256>>>(w_ih, pWih, n2); }
    k_embed<<<(SB*EMBD/2+255)/256,256>>>(x, emb);
    k_inith<<<(BATCH*HID+255)/256,256>>>(hidden);

    // gi = relu(E) @ w_ih^T + b_ih   (4096 x 3072, K=512)
    k_gemm<false><<<dim3(SB/GBM, H3/GBN), 256, G_SMEM>>>(pE, pWih, b_ih, pGi, EMBD, H3);

    // sequential GRU
    k_recur<<<RC_CTAS, 256, RC_SMEM>>>(w_hh, b_hh, hidden);

    // logits = hs @ w_out^T + b_out, rows permuted (s,b) -> (b,s)
    k_gemm<true><<<dim3(SB/GBM, VOCAB/GBN), 256, G_SMEM>>>(pHs, pWout, b_out, out, HID, VOCAB);
}

// round 10
// speedup vs baseline: 1.1883x; 1.0579x over previous
#include <cuda_runtime.h>
#include <cuda_fp16.h>
#include <cstdint>

#define SEQ   64
#define BATCH 64
#define EMBD  512
#define HID   1024
#define VOCAB 32000
#define SB    (SEQ*BATCH)
#define H3    (3*HID)

// ---------------- device scratch ----------------
__device__ __half g_E[SB*EMBD];
__device__ __half g_wih[H3*EMBD];
__device__ __half g_wout[(size_t)VOCAB*HID];
__device__ float  g_gi[(size_t)SB*H3];
__device__ __half g_hs[(size_t)SB*HID];
__device__ __half g_h16[2][BATCH*HID];
__device__ unsigned g_bar_count = 0;
__device__ volatile unsigned g_bar_sense = 0;
__device__ volatile int g_flag = 0;

// ---------------- ptx helpers ----------------
__device__ __forceinline__ uint32_t smem_u32(const void* p){
    return (uint32_t)__cvta_generic_to_shared(p);
}
__device__ __forceinline__ void ldsm_x4(uint32_t&a0,uint32_t&a1,uint32_t&a2,uint32_t&a3,uint32_t addr){
    asm volatile("ldmatrix.sync.aligned.m8n8.x4.shared.b16 {%0,%1,%2,%3},[%4];"
                 :"=r"(a0),"=r"(a1),"=r"(a2),"=r"(a3):"r"(addr));
}
__device__ __forceinline__ void ldsm_x2(uint32_t&b0,uint32_t&b1,uint32_t addr){
    asm volatile("ldmatrix.sync.aligned.m8n8.x2.shared.b16 {%0,%1},[%2];"
                 :"=r"(b0),"=r"(b1):"r"(addr));
}
__device__ __forceinline__ void mma16816(float&d0,float&d1,float&d2,float&d3,
                                         uint32_t a0,uint32_t a1,uint32_t a2,uint32_t a3,
                                         uint32_t b0,uint32_t b1){
    asm volatile("mma.sync.aligned.m16n8k16.row.col.f32.f16.f16.f32 "
                 "{%0,%1,%2,%3},{%4,%5,%6,%7},{%8,%9},{%0,%1,%2,%3};"
                 :"+f"(d0),"+f"(d1),"+f"(d2),"+f"(d3)
                 :"r"(a0),"r"(a1),"r"(a2),"r"(a3),"r"(b0),"r"(b1));
}
__device__ __forceinline__ void cp16(uint32_t saddr, const void* g){
    asm volatile("cp.async.cg.shared.global [%0],[%1],16;"::"r"(saddr),"l"(g));
}
__device__ __forceinline__ void cp_commit(){ asm volatile("cp.async.commit_group;"); }
template<int N> __device__ __forceinline__ void cp_wait(){ asm volatile("cp.async.wait_group %0;"::"n"(N)); }

// ---------------- prep kernels ----------------
__global__ void k_cvt(const float* __restrict__ src, __half* __restrict__ dst, int n2){
    int i = blockIdx.x*blockDim.x + threadIdx.x;
    if (i < n2){
        float2 v = reinterpret_cast<const float2*>(src)[i];
        reinterpret_cast<__half2*>(dst)[i] = __floats2half2_rn(v.x, v.y);
    }
}
__global__ void k_embed(const int* __restrict__ x, const float* __restrict__ emb){
    int i = blockIdx.x*blockDim.x + threadIdx.x;
    if (i >= SB*EMBD/2) return;
    int row = i/(EMBD/2), cp = i%(EMBD/2);
    int s = row>>6, b = row&63;
    int tok = (s==0) ? 2 : x[(s-1)*BATCH + b];
    float2 v = reinterpret_cast<const float2*>(emb + (size_t)tok*EMBD)[cp];
    float a0 = (tok==0)?0.f:fmaxf(v.x,0.f);
    float a1 = (tok==0)?0.f:fmaxf(v.y,0.f);
    reinterpret_cast<__half2*>(g_E)[i] = __floats2half2_rn(a0, a1);
}
__global__ void k_inith(const float* __restrict__ hidden){
    int i = blockIdx.x*blockDim.x + threadIdx.x;
    if (i < BATCH*HID) g_h16[0][i] = __float2half(hidden[i]);
    if (i == 0){ g_bar_count = 0; g_bar_sense = 0; g_flag = 0; }
}

// ---------------- gi GEMM (cp.async HMMA, BM=BN=128, BK=64, occ2) ----------------
#define GBM 128
#define GBN 128
#define GBK 64
#define ROWB 144
#define STG_ROWS (GBM+GBN)           // 256
#define STG_BYTES (STG_ROWS*ROWB)    // 36864
#define G_SMEM (2*STG_BYTES)         // 73728

__global__ __launch_bounds__(256,2)
void k_gemm(const __half* __restrict__ A, const __half* __restrict__ Bw,
            const float* __restrict__ bias, float* __restrict__ C, int K, int N){
    extern __shared__ char smem[];
    uint32_t sbase = smem_u32(smem);
    int tid = threadIdx.x;
    int bm = blockIdx.x, bn = blockIdx.y;
    const __half* Ab = A + (size_t)bm*GBM*K;
    const __half* Bb = Bw + (size_t)bn*GBN*K;

    int NK = K/GBK;
    auto load_stage = [&](int i){
        uint32_t stg = sbase + (i&1)*STG_BYTES;
        #pragma unroll
        for (int t=0;t<8;t++){
            int c = tid + t*256;
            int row = c>>3, c16 = c&7;
            const __half* src = (row < GBM)
                ? (Ab + (size_t)row*K + i*GBK + c16*8)
                : (Bb + (size_t)(row-GBM)*K + i*GBK + c16*8);
            cp16(stg + row*ROWB + c16*16, src);
        }
        cp_commit();
    };
    load_stage(0); load_stage(1);

    int warp = tid>>5, lane = tid&31;
    int wm = warp&1, wn = warp>>1;
    float acc[4][4][4];
    #pragma unroll
    for(int mi=0;mi<4;mi++) for(int ni=0;ni<4;ni++) for(int d=0;d<4;d++) acc[mi][ni][d]=0.f;

    for (int i=0; i<NK; i++){
        if (i <= NK-2) cp_wait<1>(); else cp_wait<0>();
        __syncthreads();
        uint32_t sA = sbase + (i&1)*STG_BYTES;
        uint32_t sB = sA + GBM*ROWB;
        #pragma unroll
        for (int k16=0; k16<GBK/16; k16++){
            uint32_t a[4][4], b[2][4];
            #pragma unroll
            for(int mi=0;mi<4;mi++){
                int row = wm*64 + mi*16 + (lane&15);
                int col = (k16*16 + (lane>>4)*8)*2;
                ldsm_x4(a[mi][0],a[mi][1],a[mi][2],a[mi][3], sA + row*ROWB + col);
            }
            #pragma unroll
            for(int nj=0;nj<2;nj++){
                int row = wn*32 + nj*16 + ((lane>>4)*8) + (lane&7);
                int col = (k16*16 + ((lane>>3)&1)*8)*2;
                ldsm_x4(b[nj][0],b[nj][1],b[nj][2],b[nj][3], sB + row*ROWB + col);
            }
            #pragma unroll
            for(int mi=0;mi<4;mi++)
                #pragma unroll
                for(int nj=0;nj<2;nj++){
                    mma16816(acc[mi][2*nj][0],acc[mi][2*nj][1],acc[mi][2*nj][2],acc[mi][2*nj][3],
                             a[mi][0],a[mi][1],a[mi][2],a[mi][3], b[nj][0],b[nj][1]);
                    mma16816(acc[mi][2*nj+1][0],acc[mi][2*nj+1][1],acc[mi][2*nj+1][2],acc[mi][2*nj+1][3],
                             a[mi][0],a[mi][1],a[mi][2],a[mi][3], b[nj][2],b[nj][3]);
                }
        }
        __syncthreads();
        if (i + 2 < NK) load_stage(i + 2);
    }

    int mbase = bm*GBM + wm*64;
    int nbase = bn*GBN + wn*32;
    #pragma unroll
    for(int mi=0;mi<4;mi++){
        int r0 = mbase + mi*16 + (lane>>2);
        #pragma unroll
        for(int ni=0;ni<4;ni++){
            int cc = nbase + ni*8 + 2*(lane&3);
            float bv0 = bias[cc], bv1 = bias[cc+1];
            *reinterpret_cast<float2*>(C + (size_t)r0*N + cc) =
                make_float2(acc[mi][ni][0]+bv0, acc[mi][ni][1]+bv1);
            *reinterpret_cast<float2*>(C + (size_t)(r0+8)*N + cc) =
                make_float2(acc[mi][ni][2]+bv0, acc[mi][ni][3]+bv1);
        }
    }
}

// ---------------- fused recurrence + projection ----------------
// Grid = 296 CTAs (2/SM). CTAs [0,128): recurrence (j-slice of 8) then tail proj tiles.
// CTAs [128,296): projection tiles, flag-gated on recurrence steps.
#define RECUR_CTAS 128
#define PROJ_CTAS  168
#define TOT_CTAS   (RECUR_CTAS+PROJ_CTAS)
#define NT_BM      (SB/GBM)            // 32
#define NT_BN      (VOCAB/GBN)         // 250
#define NT_TILES   (NT_BM*NT_BN)       // 8000
#define P_SPLIT    5056                // proj CTAs take [0,P), recur CTAs take [P,8000)
#define F_SMEM     73728

// one projection tile: out[perm(bm rows), bn cols] = hs_tile @ wout_tile^T + bias
__device__ __forceinline__ void proj_tile(uint32_t sbase, int bm, int bn, int tid,
                                          const __half* __restrict__ Apool,
                                          const __half* __restrict__ Bw,
                                          const float* __restrict__ bias,
                                          float* __restrict__ C){
    const __half* Ab = Apool + (size_t)bm*GBM*HID;
    const __half* Bb = Bw + (size_t)bn*GBN*HID;
    const int NK = HID/GBK;  // 16
    auto load_stage = [&](int i){
        uint32_t stg = sbase + (i&1)*STG_BYTES;
        #pragma unroll
        for (int t=0;t<8;t++){
            int c = tid + t*256;
            int row = c>>3, c16 = c&7;
            const __half* src = (row < GBM)
                ? (Ab + (size_t)row*HID + i*GBK + c16*8)
                : (Bb + (size_t)(row-GBM)*HID + i*GBK + c16*8);
            cp16(stg + row*ROWB + c16*16, src);
        }
        cp_commit();
    };
    load_stage(0); load_stage(1);

    int warp = tid>>5, lane = tid&31;
    int wm = warp&1, wn = warp>>1;
    float acc[4][4][4];
    #pragma unroll
    for(int mi=0;mi<4;mi++) for(int ni=0;ni<4;ni++) for(int d=0;d<4;d++) acc[mi][ni][d]=0.f;

    for (int i=0; i<NK; i++){
        if (i <= NK-2) cp_wait<1>(); else cp_wait<0>();
        __syncthreads();
        uint32_t sA = sbase + (i&1)*STG_BYTES;
        uint32_t sB = sA + GBM*ROWB;
        #pragma unroll
        for (int k16=0; k16<GBK/16; k16++){
            uint32_t a[4][4], b[2][4];
            #pragma unroll
            for(int mi=0;mi<4;mi++){
                int row = wm*64 + mi*16 + (lane&15);
                int col = (k16*16 + (lane>>4)*8)*2;
                ldsm_x4(a[mi][0],a[mi][1],a[mi][2],a[mi][3], sA + row*ROWB + col);
            }
            #pragma unroll
            for(int nj=0;nj<2;nj++){
                int row = wn*32 + nj*16 + ((lane>>4)*8) + (lane&7);
                int col = (k16*16 + ((lane>>3)&1)*8)*2;
                ldsm_x4(b[nj][0],b[nj][1],b[nj][2],b[nj][3], sB + row*ROWB + col);
            }
            #pragma unroll
            for(int mi=0;mi<4;mi++)
                #pragma unroll
                for(int nj=0;nj<2;nj++){
                    mma16816(acc[mi][2*nj][0],acc[mi][2*nj][1],acc[mi][2*nj][2],acc[mi][2*nj][3],
                             a[mi][0],a[mi][1],a[mi][2],a[mi][3], b[nj][0],b[nj][1]);
                    mma16816(acc[mi][2*nj+1][0],acc[mi][2*nj+1][1],acc[mi][2*nj+1][2],acc[mi][2*nj+1][3],
                             a[mi][0],a[mi][1],a[mi][2],a[mi][3], b[nj][2],b[nj][3]);
                }
        }
        __syncthreads();
        if (i + 2 < NK) load_stage(i + 2);
    }

    int mbase = bm*GBM + wm*64;
    int nbase = bn*GBN + wn*32;
    #pragma unroll
    for(int mi=0;mi<4;mi++){
        int r0 = mbase + mi*16 + (lane>>2);
        #pragma unroll
        for(int ni=0;ni<4;ni++){
            int cc = nbase + ni*8 + 2*(lane&3);
            float bv0 = bias[cc], bv1 = bias[cc+1];
            int rr = r0;
            size_t ro = (size_t)((rr&63)*64 + (rr>>6))*VOCAB;
            *reinterpret_cast<float2*>(C + ro + cc) = make_float2(acc[mi][ni][0]+bv0, acc[mi][ni][1]+bv1);
            rr = r0+8;
            ro = (size_t)((rr&63)*64 + (rr>>6))*VOCAB;
            *reinterpret_cast<float2*>(C + ro + cc) = make_float2(acc[mi][ni][2]+bv0, acc[mi][ni][3]+bv1);
        }
    }
}

__device__ __forceinline__ void wait_flag(int need, int tid){
    if (tid == 0){
        while (g_flag < need) __nanosleep(128);
        __threadfence();
    }
    __syncthreads();
}

__global__ __launch_bounds__(256,2)
void k_fused(const float* __restrict__ w_hh, const float* __restrict__ b_hh,
             const float* __restrict__ hidden,
             const __half* __restrict__ wout, const float* __restrict__ b_out,
             float* __restrict__ out){
    extern __shared__ char smem[];
    uint32_t sbase = smem_u32(smem);
    int tid = threadIdx.x;
    int cta = blockIdx.x;

    if (cta < RECUR_CTAS){
        // ===== recurrence: j-slice [cta*8, cta*8+8) =====
        __half* sW  = (__half*)smem;                    // 24 x stride1032 halfs = 49536B
        __half* sH  = (__half*)(smem + 49536);          // 64 x stride136 halfs = 17408B
        float*  sGH = (float*)(smem + 66944);           // 64 x 24 f32 = 6144B
        int j0 = cta*8;

        for (int idx = tid; idx < 24*HID; idx += 256){
            int r = idx>>10, k = idx&1023;
            int g = r>>3, jr = r&7;
            sW[r*1032 + k] = __float2half(w_hh[(size_t)(g*HID + j0 + jr)*HID + k]);
        }
        float bh0[2], bh1[2], bh2[2], hold[2];
        #pragma unroll
        for (int t=0;t<2;t++){
            int o = tid + t*256; int b = o>>3, jj = o&7; int j = j0+jj;
            bh0[t]=b_hh[j]; bh1[t]=b_hh[HID+j]; bh2[t]=b_hh[2*HID+j];
            hold[t]=hidden[b*HID + j];
        }
        int warp = tid>>5, lane = tid&31;
        int wm = warp&3, wn = warp>>2;      // wm: batch 16-block; wn0: n[0,16), wn1: n[16,24)
        int nacc = (wn==0)?2:1;
        __syncthreads();

        for (int s=0; s<SEQ; s++){
            const __half* hb = g_h16[s&1];
            float acc[2][4];
            #pragma unroll
            for(int q=0;q<2;q++) for(int d=0;d<4;d++) acc[q][d]=0.f;

            for (int ch=0; ch<8; ch++){
                __syncthreads();
                #pragma unroll
                for (int i=0;i<4;i++){
                    int lin = tid + i*256;
                    int row = lin>>4, c8 = lin&15;
                    uint4 v = __ldcg(reinterpret_cast<const uint4*>(hb + row*HID + ch*128 + c8*8));
                    *reinterpret_cast<uint4*>(&sH[row*136 + c8*8]) = v;
                }
                __syncthreads();
                #pragma unroll
                for (int k16=0;k16<8;k16++){
                    uint32_t a0,a1,a2,a3;
                    int arow = wm*16 + (lane&15);
                    int acol = k16*16 + (lane>>4)*8;
                    ldsm_x4(a0,a1,a2,a3, smem_u32(&sH[arow*136 + acol]));
                    #pragma unroll
                    for (int q=0;q<2;q++){
                        if (q < nacc){
                            int ni = wn*2 + q;
                            uint32_t b0,b1;
                            int brow = ni*8 + (lane&7);
                            int bcol = ch*128 + k16*16 + ((lane>>3)&1)*8;
                            ldsm_x2(b0,b1, smem_u32(&sW[brow*1032 + bcol]));
                            mma16816(acc[q][0],acc[q][1],acc[q][2],acc[q][3],a0,a1,a2,a3,b0,b1);
                        }
                    }
                }
            }
            // gh -> sGH
            {
                int r = wm*16 + (lane>>2);
                #pragma unroll
                for (int q=0;q<2;q++){
                    if (q < nacc){
                        int ni = wn*2 + q;
                        int cc = ni*8 + 2*(lane&3);
                        sGH[r*24 + cc]       = acc[q][0];
                        sGH[r*24 + cc+1]     = acc[q][1];
                        sGH[(r+8)*24 + cc]   = acc[q][2];
                        sGH[(r+8)*24 + cc+1] = acc[q][3];
                    }
                }
            }
            __syncthreads();
            // gates
            __half* hwr = g_h16[(s+1)&1];
            #pragma unroll
            for (int t=0;t<2;t++){
                int o = tid + t*256; int b = o>>3, jj = o&7; int j = j0+jj;
                const float* gi = g_gi + (size_t)(s*BATCH + b)*H3;
                float ir = gi[j], iz = gi[HID+j], inn = gi[2*HID+j];
                float hr = sGH[b*24+jj]    + bh0[t];
                float hz = sGH[b*24+8+jj]  + bh1[t];
                float hn = sGH[b*24+16+jj] + bh2[t];
                float rg = 1.f/(1.f+__expf(-(ir+hr)));
                float zg = 1.f/(1.f+__expf(-(iz+hz)));
                float ng = tanhf(inn + rg*hn);
                float hnew = (1.f - zg)*ng + zg*hold[t];
                hold[t] = hnew;
                unsigned short hb16 = __half_as_ushort(__float2half(hnew));
                __stcg(reinterpret_cast<unsigned short*>(hwr + b*HID + j), hb16);
                __stcg(reinterpret_cast<unsigned short*>(g_hs + (size_t)(s*BATCH + b)*HID + j), hb16);
            }
            // grid barrier over recurrence CTAs + publish step flag
            __threadfence();
            __syncthreads();
            if (tid==0){
                unsigned old = g_bar_sense;
                unsigned a = atomicAdd(&g_bar_count, 1u);
                if (a == RECUR_CTAS-1){
                    g_bar_count = 0;
                    g_flag = s+1;
                    __threadfence();
                    atomicExch((unsigned*)&g_bar_sense, old+1u);
                } else {
                    while (g_bar_sense == old) __nanosleep(32);
                }
                __threadfence();
            }
            __syncthreads();
        }
        // ===== tail projection tiles =====
        __syncthreads();
        __half* pHs;  // g_hs seen via symbol directly
        pHs = g_hs;
        for (int t = P_SPLIT + cta; t < NT_TILES; t += RECUR_CTAS){
            int bm = t / NT_BN, bn = t % NT_BN;
            proj_tile(sbase, bm, bn, tid, pHs, wout, b_out, out);
        }
    } else {
        // ===== projection CTAs, flag-gated =====
        int pidx = cta - RECUR_CTAS;
        for (int t = pidx; t < P_SPLIT; t += PROJ_CTAS){
            int bm = t / NT_BN, bn = t % NT_BN;
            wait_flag(2*bm + 2, tid);
            proj_tile(sbase, bm, bn, tid, g_hs, wout, b_out, out);
        }
    }
}

// ---------------- launch ----------------
extern "C" void kernel_launch(void* const* d_in, const int* in_sizes, int n_in,
                              void* d_out, int out_size){
    const int*   x      = (const int*)  d_in[0];
    const float* hidden = (const float*)d_in[1];
    const float* emb    = (const float*)d_in[2];
    const float* w_ih   = (const float*)d_in[3];
    const float* w_hh   = (const float*)d_in[4];
    const float* b_ih   = (const float*)d_in[5];
    const float* b_hh   = (const float*)d_in[6];
    const float* w_out  = (const float*)d_in[7];
    const float* b_out  = (const float*)d_in[8];
    float* out = (float*)d_out;

    __half *pE, *pWih, *pWout;
    float  *pGi;
    cudaGetSymbolAddress((void**)&pE,    g_E);
    cudaGetSymbolAddress((void**)&pWih,  g_wih);
    cudaGetSymbolAddress((void**)&pWout, g_wout);
    cudaGetSymbolAddress((void**)&pGi,   g_gi);

    cudaFuncSetAttribute(k_gemm,  cudaFuncAttributeMaxDynamicSharedMemorySize, G_SMEM);
    cudaFuncSetAttribute(k_fused, cudaFuncAttributeMaxDynamicSharedMemorySize, F_SMEM);

    {   int n2 = (int)((size_t)VOCAB*HID/2);
        k_cvt<<<(n2+255)/256,256>>>(w_out, pWout, n2); }
    {   int n2 = H3*EMBD/2;
        k_cvt<<<(n2+255)/256,256>>>(w_ih, pWih, n2); }
    k_embed<<<(SB*EMBD/2+255)/256,256>>>(x, emb);
    k_inith<<<(BATCH*HID+255)/256,256>>>(hidden);

    // gi = relu(E) @ w_ih^T + b_ih   (4096 x 3072, K=512)
    k_gemm<<<dim3(SB/GBM, H3/GBN), 256, G_SMEM>>>(pE, pWih, b_ih, pGi, EMBD, H3);

    // fused recurrence + projection
    k_fused<<<TOT_CTAS, 256, F_SMEM>>>(w_hh, b_hh, hidden, pWout, b_out, out);
}

// round 11
// speedup vs baseline: 1.2389x; 1.0426x over previous
#include <cuda_runtime.h>
#include <cuda_fp16.h>
#include <cstdint>

#define SEQ   64
#define BATCH 64
#define EMBD  512
#define HID   1024
#define VOCAB 32000
#define SB    (SEQ*BATCH)
#define H3    (3*HID)

// ---------------- device scratch ----------------
__device__ __half g_E[SB*EMBD];
__device__ __half g_wih[H3*EMBD];
__device__ __half g_wout[(size_t)VOCAB*HID];
__device__ float  g_gi[(size_t)SB*H3];
__device__ __half g_hs[(size_t)SB*HID];
__device__ __half g_h16[2][BATCH*HID];
__device__ unsigned g_bar_count = 0;
__device__ volatile unsigned g_bar_sense = 0;
__device__ volatile int g_flag = 0;
__device__ volatile unsigned g_pcount = 0;

// ---------------- ptx helpers ----------------
__device__ __forceinline__ uint32_t smem_u32(const void* p){
    return (uint32_t)__cvta_generic_to_shared(p);
}
__device__ __forceinline__ void ldsm_x4(uint32_t&a0,uint32_t&a1,uint32_t&a2,uint32_t&a3,uint32_t addr){
    asm volatile("ldmatrix.sync.aligned.m8n8.x4.shared.b16 {%0,%1,%2,%3},[%4];"
                 :"=r"(a0),"=r"(a1),"=r"(a2),"=r"(a3):"r"(addr));
}
__device__ __forceinline__ void ldsm_x2(uint32_t&b0,uint32_t&b1,uint32_t addr){
    asm volatile("ldmatrix.sync.aligned.m8n8.x2.shared.b16 {%0,%1},[%2];"
                 :"=r"(b0),"=r"(b1):"r"(addr));
}
__device__ __forceinline__ void mma16816(float&d0,float&d1,float&d2,float&d3,
                                         uint32_t a0,uint32_t a1,uint32_t a2,uint32_t a3,
                                         uint32_t b0,uint32_t b1){
    asm volatile("mma.sync.aligned.m16n8k16.row.col.f32.f16.f16.f32 "
                 "{%0,%1,%2,%3},{%4,%5,%6,%7},{%8,%9},{%0,%1,%2,%3};"
                 :"+f"(d0),"+f"(d1),"+f"(d2),"+f"(d3)
                 :"r"(a0),"r"(a1),"r"(a2),"r"(a3),"r"(b0),"r"(b1));
}
__device__ __forceinline__ void cp16(uint32_t saddr, const void* g){
    asm volatile("cp.async.cg.shared.global [%0],[%1],16;"::"r"(saddr),"l"(g));
}
__device__ __forceinline__ void cp_commit(){ asm volatile("cp.async.commit_group;"); }
template<int N> __device__ __forceinline__ void cp_wait(){ asm volatile("cp.async.wait_group %0;"::"n"(N)); }

// ---------------- prep kernels ----------------
__global__ void k_cvt(const float* __restrict__ src, __half* __restrict__ dst, int n2){
    int i = blockIdx.x*blockDim.x + threadIdx.x;
    if (i < n2){
        float2 v = reinterpret_cast<const float2*>(src)[i];
        reinterpret_cast<__half2*>(dst)[i] = __floats2half2_rn(v.x, v.y);
    }
}
__global__ void k_embed(const int* __restrict__ x, const float* __restrict__ emb){
    int i = blockIdx.x*blockDim.x + threadIdx.x;
    if (i >= SB*EMBD/2) return;
    int row = i/(EMBD/2), cp = i%(EMBD/2);
    int s = row>>6, b = row&63;
    int tok = (s==0) ? 2 : x[(s-1)*BATCH + b];
    float2 v = reinterpret_cast<const float2*>(emb + (size_t)tok*EMBD)[cp];
    float a0 = (tok==0)?0.f:fmaxf(v.x,0.f);
    float a1 = (tok==0)?0.f:fmaxf(v.y,0.f);
    reinterpret_cast<__half2*>(g_E)[i] = __floats2half2_rn(a0, a1);
}
__global__ void k_inith(const float* __restrict__ hidden){
    int i = blockIdx.x*blockDim.x + threadIdx.x;
    if (i < BATCH*HID) g_h16[0][i] = __float2half(hidden[i]);
    if (i == 0){ g_bar_count = 0; g_bar_sense = 0; g_flag = 0; g_pcount = 0; }
}

// ---------------- gi GEMM (cp.async HMMA, BM=BN=128, BK=64, occ2) ----------------
#define GBM 128
#define GBN 128
#define GBK 64
#define ROWB 144
#define STG_ROWS (GBM+GBN)           // 256
#define STG_BYTES (STG_ROWS*ROWB)    // 36864
#define G_SMEM (2*STG_BYTES)         // 73728

__global__ __launch_bounds__(256,2)
void k_gemm(const __half* __restrict__ A, const __half* __restrict__ Bw,
            const float* __restrict__ bias, float* __restrict__ C, int K, int N){
    extern __shared__ char smem[];
    uint32_t sbase = smem_u32(smem);
    int tid = threadIdx.x;
    int bm = blockIdx.x, bn = blockIdx.y;
    const __half* Ab = A + (size_t)bm*GBM*K;
    const __half* Bb = Bw + (size_t)bn*GBN*K;

    int NK = K/GBK;
    auto load_stage = [&](int i){
        uint32_t stg = sbase + (i&1)*STG_BYTES;
        #pragma unroll
        for (int t=0;t<8;t++){
            int c = tid + t*256;
            int row = c>>3, c16 = c&7;
            const __half* src = (row < GBM)
                ? (Ab + (size_t)row*K + i*GBK + c16*8)
                : (Bb + (size_t)(row-GBM)*K + i*GBK + c16*8);
            cp16(stg + row*ROWB + c16*16, src);
        }
        cp_commit();
    };
    load_stage(0); load_stage(1);

    int warp = tid>>5, lane = tid&31;
    int wm = warp&1, wn = warp>>1;
    float acc[4][4][4];
    #pragma unroll
    for(int mi=0;mi<4;mi++) for(int ni=0;ni<4;ni++) for(int d=0;d<4;d++) acc[mi][ni][d]=0.f;

    for (int i=0; i<NK; i++){
        if (i <= NK-2) cp_wait<1>(); else cp_wait<0>();
        __syncthreads();
        uint32_t sA = sbase + (i&1)*STG_BYTES;
        uint32_t sB = sA + GBM*ROWB;
        #pragma unroll
        for (int k16=0; k16<GBK/16; k16++){
            uint32_t a[4][4], b[2][4];
            #pragma unroll
            for(int mi=0;mi<4;mi++){
                int row = wm*64 + mi*16 + (lane&15);
                int col = (k16*16 + (lane>>4)*8)*2;
                ldsm_x4(a[mi][0],a[mi][1],a[mi][2],a[mi][3], sA + row*ROWB + col);
            }
            #pragma unroll
            for(int nj=0;nj<2;nj++){
                int row = wn*32 + nj*16 + ((lane>>4)*8) + (lane&7);
                int col = (k16*16 + ((lane>>3)&1)*8)*2;
                ldsm_x4(b[nj][0],b[nj][1],b[nj][2],b[nj][3], sB + row*ROWB + col);
            }
            #pragma unroll
            for(int mi=0;mi<4;mi++)
                #pragma unroll
                for(int nj=0;nj<2;nj++){
                    mma16816(acc[mi][2*nj][0],acc[mi][2*nj][1],acc[mi][2*nj][2],acc[mi][2*nj][3],
                             a[mi][0],a[mi][1],a[mi][2],a[mi][3], b[nj][0],b[nj][1]);
                    mma16816(acc[mi][2*nj+1][0],acc[mi][2*nj+1][1],acc[mi][2*nj+1][2],acc[mi][2*nj+1][3],
                             a[mi][0],a[mi][1],a[mi][2],a[mi][3], b[nj][2],b[nj][3]);
                }
        }
        __syncthreads();
        if (i + 2 < NK) load_stage(i + 2);
    }

    int mbase = bm*GBM + wm*64;
    int nbase = bn*GBN + wn*32;
    #pragma unroll
    for(int mi=0;mi<4;mi++){
        int r0 = mbase + mi*16 + (lane>>2);
        #pragma unroll
        for(int ni=0;ni<4;ni++){
            int cc = nbase + ni*8 + 2*(lane&3);
            float bv0 = bias[cc], bv1 = bias[cc+1];
            *reinterpret_cast<float2*>(C + (size_t)r0*N + cc) =
                make_float2(acc[mi][ni][0]+bv0, acc[mi][ni][1]+bv1);
            *reinterpret_cast<float2*>(C + (size_t)(r0+8)*N + cc) =
                make_float2(acc[mi][ni][2]+bv0, acc[mi][ni][3]+bv1);
        }
    }
}

// ---------------- fused recurrence + projection ----------------
#define RECUR_CTAS 128
#define PROJ_CTAS  168
#define TOT_CTAS   (RECUR_CTAS+PROJ_CTAS)
#define NT_BM      (SB/GBM)            // 32
#define NT_BN      (VOCAB/GBN)         // 250
#define NT_TILES   (NT_BM*NT_BN)       // 8000
#define P_SPLIT    4992
#define F_SMEM     73728
#define WOUT_N2    ((int)((size_t)VOCAB*HID/2))   // 16,384,000 half2

__device__ __forceinline__ void proj_tile(uint32_t sbase, int bm, int bn, int tid,
                                          const __half* __restrict__ Apool,
                                          const __half* __restrict__ Bw,
                                          const float* __restrict__ bias,
                                          float* __restrict__ C){
    const __half* Ab = Apool + (size_t)bm*GBM*HID;
    const __half* Bb = Bw + (size_t)bn*GBN*HID;
    const int NK = HID/GBK;  // 16
    auto load_stage = [&](int i){
        uint32_t stg = sbase + (i&1)*STG_BYTES;
        #pragma unroll
        for (int t=0;t<8;t++){
            int c = tid + t*256;
            int row = c>>3, c16 = c&7;
            const __half* src = (row < GBM)
                ? (Ab + (size_t)row*HID + i*GBK + c16*8)
                : (Bb + (size_t)(row-GBM)*HID + i*GBK + c16*8);
            cp16(stg + row*ROWB + c16*16, src);
        }
        cp_commit();
    };
    load_stage(0); load_stage(1);

    int warp = tid>>5, lane = tid&31;
    int wm = warp&1, wn = warp>>1;
    float acc[4][4][4];
    #pragma unroll
    for(int mi=0;mi<4;mi++) for(int ni=0;ni<4;ni++) for(int d=0;d<4;d++) acc[mi][ni][d]=0.f;

    for (int i=0; i<NK; i++){
        if (i <= NK-2) cp_wait<1>(); else cp_wait<0>();
        __syncthreads();
        uint32_t sA = sbase + (i&1)*STG_BYTES;
        uint32_t sB = sA + GBM*ROWB;
        #pragma unroll
        for (int k16=0; k16<GBK/16; k16++){
            uint32_t a[4][4], b[2][4];
            #pragma unroll
            for(int mi=0;mi<4;mi++){
                int row = wm*64 + mi*16 + (lane&15);
                int col = (k16*16 + (lane>>4)*8)*2;
                ldsm_x4(a[mi][0],a[mi][1],a[mi][2],a[mi][3], sA + row*ROWB + col);
            }
            #pragma unroll
            for(int nj=0;nj<2;nj++){
                int row = wn*32 + nj*16 + ((lane>>4)*8) + (lane&7);
                int col = (k16*16 + ((lane>>3)&1)*8)*2;
                ldsm_x4(b[nj][0],b[nj][1],b[nj][2],b[nj][3], sB + row*ROWB + col);
            }
            #pragma unroll
            for(int mi=0;mi<4;mi++)
                #pragma unroll
                for(int nj=0;nj<2;nj++){
                    mma16816(acc[mi][2*nj][0],acc[mi][2*nj][1],acc[mi][2*nj][2],acc[mi][2*nj][3],
                             a[mi][0],a[mi][1],a[mi][2],a[mi][3], b[nj][0],b[nj][1]);
                    mma16816(acc[mi][2*nj+1][0],acc[mi][2*nj+1][1],acc[mi][2*nj+1][2],acc[mi][2*nj+1][3],
                             a[mi][0],a[mi][1],a[mi][2],a[mi][3], b[nj][2],b[nj][3]);
                }
        }
        __syncthreads();
        if (i + 2 < NK) load_stage(i + 2);
    }

    int mbase = bm*GBM + wm*64;
    int nbase = bn*GBN + wn*32;
    #pragma unroll
    for(int mi=0;mi<4;mi++){
        int r0 = mbase + mi*16 + (lane>>2);
        #pragma unroll
        for(int ni=0;ni<4;ni++){
            int cc = nbase + ni*8 + 2*(lane&3);
            float bv0 = bias[cc], bv1 = bias[cc+1];
            int rr = r0;
            size_t ro = (size_t)((rr&63)*64 + (rr>>6))*VOCAB;
            *reinterpret_cast<float2*>(C + ro + cc) = make_float2(acc[mi][ni][0]+bv0, acc[mi][ni][1]+bv1);
            rr = r0+8;
            ro = (size_t)((rr&63)*64 + (rr>>6))*VOCAB;
            *reinterpret_cast<float2*>(C + ro + cc) = make_float2(acc[mi][ni][2]+bv0, acc[mi][ni][3]+bv1);
        }
    }
}

__device__ __forceinline__ void wait_flag(int need, int tid){
    if (tid == 0){
        while (g_flag < need) __nanosleep(128);
        __threadfence();
    }
    __syncthreads();
}
__device__ __forceinline__ void wait_pcount(int tid){
    if (tid == 0){
        while (g_pcount < PROJ_CTAS) __nanosleep(128);
        __threadfence();
    }
    __syncthreads();
}

__global__ __launch_bounds__(256,2)
void k_fused(const float* __restrict__ w_hh, const float* __restrict__ b_hh,
             const float* __restrict__ hidden,
             const float* __restrict__ w_out_f32, const float* __restrict__ b_out,
             float* __restrict__ out){
    extern __shared__ char smem[];
    uint32_t sbase = smem_u32(smem);
    int tid = threadIdx.x;
    int cta = blockIdx.x;

    if (cta < RECUR_CTAS){
        // ===== recurrence: j-slice [cta*8, cta*8+8) =====
        __half* sW  = (__half*)smem;                    // 24 x 1032 halfs
        __half* sH  = (__half*)(smem + 49536);          // 64 x 136 halfs
        float*  sGH = (float*)(smem + 66944);           // 64 x 24 f32
        int j0 = cta*8;

        for (int idx = tid; idx < 24*HID; idx += 256){
            int r = idx>>10, k = idx&1023;
            int g = r>>3, jr = r&7;
            sW[r*1032 + k] = __float2half(w_hh[(size_t)(g*HID + j0 + jr)*HID + k]);
        }
        float bh0[2], bh1[2], bh2[2], hold[2];
        #pragma unroll
        for (int t=0;t<2;t++){
            int o = tid + t*256; int b = o>>3, jj = o&7; int j = j0+jj;
            bh0[t]=b_hh[j]; bh1[t]=b_hh[HID+j]; bh2[t]=b_hh[2*HID+j];
            hold[t]=hidden[b*HID + j];
        }
        int warp = tid>>5, lane = tid&31;
        int wm = warp&3, wn = warp>>2;
        int nacc = (wn==0)?2:1;
        __syncthreads();

        for (int s=0; s<SEQ; s++){
            const __half* hb = g_h16[s&1];
            float acc[2][4];
            #pragma unroll
            for(int q=0;q<2;q++) for(int d=0;d<4;d++) acc[q][d]=0.f;

            for (int ch=0; ch<8; ch++){
                __syncthreads();
                #pragma unroll
                for (int i=0;i<4;i++){
                    int lin = tid + i*256;
                    int row = lin>>4, c8 = lin&15;
                    uint4 v = __ldcg(reinterpret_cast<const uint4*>(hb + row*HID + ch*128 + c8*8));
                    *reinterpret_cast<uint4*>(&sH[row*136 + c8*8]) = v;
                }
                __syncthreads();
                #pragma unroll
                for (int k16=0;k16<8;k16++){
                    uint32_t a0,a1,a2,a3;
                    int arow = wm*16 + (lane&15);
                    int acol = k16*16 + (lane>>4)*8;
                    ldsm_x4(a0,a1,a2,a3, smem_u32(&sH[arow*136 + acol]));
                    #pragma unroll
                    for (int q=0;q<2;q++){
                        if (q < nacc){
                            int ni = wn*2 + q;
                            uint32_t b0,b1;
                            int brow = ni*8 + (lane&7);
                            int bcol = ch*128 + k16*16 + ((lane>>3)&1)*8;
                            ldsm_x2(b0,b1, smem_u32(&sW[brow*1032 + bcol]));
                            mma16816(acc[q][0],acc[q][1],acc[q][2],acc[q][3],a0,a1,a2,a3,b0,b1);
                        }
                    }
                }
            }
            {
                int r = wm*16 + (lane>>2);
                #pragma unroll
                for (int q=0;q<2;q++){
                    if (q < nacc){
                        int ni = wn*2 + q;
                        int cc = ni*8 + 2*(lane&3);
                        sGH[r*24 + cc]       = acc[q][0];
                        sGH[r*24 + cc+1]     = acc[q][1];
                        sGH[(r+8)*24 + cc]   = acc[q][2];
                        sGH[(r+8)*24 + cc+1] = acc[q][3];
                    }
                }
            }
            __syncthreads();
            __half* hwr = g_h16[(s+1)&1];
            #pragma unroll
            for (int t=0;t<2;t++){
                int o = tid + t*256; int b = o>>3, jj = o&7; int j = j0+jj;
                const float* gi = g_gi + (size_t)(s*BATCH + b)*H3;
                float ir = gi[j], iz = gi[HID+j], inn = gi[2*HID+j];
                float hr = sGH[b*24+jj]    + bh0[t];
                float hz = sGH[b*24+8+jj]  + bh1[t];
                float hn = sGH[b*24+16+jj] + bh2[t];
                float rg = 1.f/(1.f+__expf(-(ir+hr)));
                float zg = 1.f/(1.f+__expf(-(iz+hz)));
                float ng = tanhf(inn + rg*hn);
                float hnew = (1.f - zg)*ng + zg*hold[t];
                hold[t] = hnew;
                unsigned short hb16 = __half_as_ushort(__float2half(hnew));
                __stcg(reinterpret_cast<unsigned short*>(hwr + b*HID + j), hb16);
                __stcg(reinterpret_cast<unsigned short*>(g_hs + (size_t)(s*BATCH + b)*HID + j), hb16);
            }
            __threadfence();
            __syncthreads();
            if (tid==0){
                unsigned old = g_bar_sense;
                unsigned a = atomicAdd(&g_bar_count, 1u);
                if (a == RECUR_CTAS-1){
                    g_bar_count = 0;
                    g_flag = s+1;
                    __threadfence();
                    atomicExch((unsigned*)&g_bar_sense, old+1u);
                } else {
                    while (g_bar_sense == old) __nanosleep(32);
                }
                __threadfence();
            }
            __syncthreads();
        }
        // ===== tail projection tiles (after wout cvt done) =====
        __syncthreads();
        wait_pcount(tid);
        for (int t = P_SPLIT + cta; t < NT_TILES; t += RECUR_CTAS){
            int bm = t / NT_BN, bn = t % NT_BN;
            proj_tile(sbase, bm, bn, tid, g_hs, g_wout, b_out, out);
        }
    } else {
        // ===== projection CTAs: first convert w_out to fp16, then gated tiles =====
        int pidx = cta - RECUR_CTAS;
        {
            const float2* src = reinterpret_cast<const float2*>(w_out_f32);
            __half2* dst = reinterpret_cast<__half2*>(g_wout);
            for (int i = pidx*256 + tid; i < WOUT_N2; i += PROJ_CTAS*256){
                float2 v = src[i];
                dst[i] = __floats2half2_rn(v.x, v.y);
            }
        }
        __threadfence();
        __syncthreads();
        if (tid == 0) atomicAdd((unsigned*)&g_pcount, 1u);
        wait_pcount(tid);

        for (int t = pidx; t < P_SPLIT; t += PROJ_CTAS){
            int bm = t / NT_BN, bn = t % NT_BN;
            wait_flag(2*bm + 2, tid);
            proj_tile(sbase, bm, bn, tid, g_hs, g_wout, b_out, out);
        }
    }
}

// ---------------- launch ----------------
extern "C" void kernel_launch(void* const* d_in, const int* in_sizes, int n_in,
                              void* d_out, int out_size){
    const int*   x      = (const int*)  d_in[0];
    const float* hidden = (const float*)d_in[1];
    const float* emb    = (const float*)d_in[2];
    const float* w_ih   = (const float*)d_in[3];
    const float* w_hh   = (const float*)d_in[4];
    const float* b_ih   = (const float*)d_in[5];
    const float* b_hh   = (const float*)d_in[6];
    const float* w_out  = (const float*)d_in[7];
    const float* b_out  = (const float*)d_in[8];
    float* out = (float*)d_out;

    __half *pE, *pWih;
    float  *pGi;
    cudaGetSymbolAddress((void**)&pE,    g_E);
    cudaGetSymbolAddress((void**)&pWih,  g_wih);
    cudaGetSymbolAddress((void**)&pGi,   g_gi);

    cudaFuncSetAttribute(k_gemm,  cudaFuncAttributeMaxDynamicSharedMemorySize, G_SMEM);
    cudaFuncSetAttribute(k_fused, cudaFuncAttributeMaxDynamicSharedMemorySize, F_SMEM);

    {   int n2 = H3*EMBD/2;
        k_cvt<<<(n2+255)/256,256>>>(w_ih, pWih, n2); }
    k_embed<<<(SB*EMBD/2+255)/256,256>>>(x, emb);
    k_inith<<<(BATCH*HID+255)/256,256>>>(hidden);

    // gi = relu(E) @ w_ih^T + b_ih   (4096 x 3072, K=512)
    k_gemm<<<dim3(SB/GBM, H3/GBN), 256, G_SMEM>>>(pE, pWih, b_ih, pGi, EMBD, H3);

    // fused: recurrence + wout-cvt + projection
    k_fused<<<TOT_CTAS, 256, F_SMEM>>>(w_hh, b_hh, hidden, w_out, b_out, out);
}